// round 4
// baseline (speedup 1.0000x reference)
#include <cuda_runtime.h>

#define BB      2
#define SS      2048
#define EE      512
#define HH      8
#define DDIM    64
#define NLAYERS 2
#define DFFN    2048
#define NROWS   4096   // BB*SS

// ---------------- scratch (device globals; no allocation allowed) ----------
__device__ float g_x[NROWS * EE];
__device__ float g_h[NROWS * EE];
__device__ float g_q[NROWS * EE];
__device__ float g_k[NROWS * EE];
__device__ float g_v[NROWS * EE];
__device__ float g_attn[NROWS * EE];
__device__ float g_ffn[NROWS * DFFN];

// ---------------- helpers ---------------------------------------------------
__device__ __forceinline__ void block_reduce2(float& s, float& s2) {
    // 128-thread block: warp shuffle reduce, then 4-partial combine in smem
    __shared__ float shm[8];
    #pragma unroll
    for (int o = 16; o > 0; o >>= 1) {
        s  += __shfl_down_sync(0xffffffffu, s,  o);
        s2 += __shfl_down_sync(0xffffffffu, s2, o);
    }
    int w = threadIdx.x >> 5;
    __syncthreads();
    if ((threadIdx.x & 31) == 0) { shm[w] = s; shm[4 + w] = s2; }
    __syncthreads();
    s  = shm[0] + shm[1] + shm[2] + shm[3];
    s2 = shm[4] + shm[5] + shm[6] + shm[7];
}

// ---------------- LayerNorm (one block / row, 128 threads, E=512) ----------
template <int AFFINE>
__global__ void ln_kernel(const float* __restrict__ in, float* __restrict__ outp,
                          const float* __restrict__ g, const float* __restrict__ b) {
    int row = blockIdx.x;
    int t = threadIdx.x;
    const float* xr = in + (size_t)row * EE;
    float v[4];
    float s = 0.f, s2 = 0.f;
    #pragma unroll
    for (int i = 0; i < 4; i++) {
        v[i] = xr[t + i * 128];
        s += v[i]; s2 += v[i] * v[i];
    }
    block_reduce2(s, s2);
    float mu  = s * (1.f / EE);
    float var = s2 * (1.f / EE) - mu * mu;
    float r   = rsqrtf(var + 1e-5f);
    #pragma unroll
    for (int i = 0; i < 4; i++) {
        int idx = t + i * 128;
        float y = (v[i] - mu) * r;
        if (AFFINE) y = y * g[idx] + b[idx];
        outp[(size_t)row * EE + idx] = y;
    }
}

// -------- fused: x += LN(attn)*g2+b2 ; h = LN_noaffine(x) -------------------
__global__ void fuse_attn_res_ln(const float* __restrict__ attn, float* x,
                                 float* __restrict__ h,
                                 const float* __restrict__ g2,
                                 const float* __restrict__ b2) {
    int row = blockIdx.x;
    int t = threadIdx.x;
    const float* ar = attn + (size_t)row * EE;
    float a[4];
    float s = 0.f, s2 = 0.f;
    #pragma unroll
    for (int i = 0; i < 4; i++) {
        a[i] = ar[t + i * 128];
        s += a[i]; s2 += a[i] * a[i];
    }
    block_reduce2(s, s2);
    float mu  = s * (1.f / EE);
    float var = s2 * (1.f / EE) - mu * mu;
    float r   = rsqrtf(var + 1e-5f);

    float xv[4];
    s = 0.f; s2 = 0.f;
    #pragma unroll
    for (int i = 0; i < 4; i++) {
        int idx = t + i * 128;
        float y = (a[i] - mu) * r * g2[idx] + b2[idx];
        float xn = x[(size_t)row * EE + idx] + y;
        x[(size_t)row * EE + idx] = xn;
        xv[i] = xn;
        s += xn; s2 += xn * xn;
    }
    block_reduce2(s, s2);
    float mu2  = s * (1.f / EE);
    float var2 = s2 * (1.f / EE) - mu2 * mu2;
    float r2   = rsqrtf(var2 + 1e-5f);
    #pragma unroll
    for (int i = 0; i < 4; i++) {
        int idx = t + i * 128;
        h[(size_t)row * EE + idx] = (xv[i] - mu2) * r2;
    }
}

// ---------------- SGEMM: C[n,j] = A[n,:] . W[j,:] + bias[j] -----------------
// A: [N,K] row-major, W: [J,K] row-major (NT gemm). Tiles 64x64x32, 256 thr.
template <int RELU, int RESADD>
__global__ __launch_bounds__(256) void gemm_nt(
    const float* __restrict__ A, const float* __restrict__ W,
    const float* __restrict__ bias, float* C,
    int K, int J, const float* res)
{
    __shared__ float sA[32][65];
    __shared__ float sB[32][65];
    int tid = threadIdx.x;
    int tm = tid >> 4, tn = tid & 15;
    int rowBase = blockIdx.y * 64;
    int colBase = blockIdx.x * 64;
    float acc[4][4] = {};
    for (int k0 = 0; k0 < K; k0 += 32) {
        #pragma unroll
        for (int i = 0; i < 8; i++) {
            int idx = tid + i * 256;       // 0..2047
            int r = idx >> 5, c = idx & 31;
            sA[c][r] = A[(size_t)(rowBase + r) * K + k0 + c];
            sB[c][r] = W[(size_t)(colBase + r) * K + k0 + c];
        }
        __syncthreads();
        #pragma unroll
        for (int kk = 0; kk < 32; kk++) {
            float a0 = sA[kk][tm * 4 + 0], a1 = sA[kk][tm * 4 + 1];
            float a2 = sA[kk][tm * 4 + 2], a3 = sA[kk][tm * 4 + 3];
            float b0 = sB[kk][tn * 4 + 0], b1 = sB[kk][tn * 4 + 1];
            float b2 = sB[kk][tn * 4 + 2], b3 = sB[kk][tn * 4 + 3];
            acc[0][0] += a0 * b0; acc[0][1] += a0 * b1; acc[0][2] += a0 * b2; acc[0][3] += a0 * b3;
            acc[1][0] += a1 * b0; acc[1][1] += a1 * b1; acc[1][2] += a1 * b2; acc[1][3] += a1 * b3;
            acc[2][0] += a2 * b0; acc[2][1] += a2 * b1; acc[2][2] += a2 * b2; acc[2][3] += a2 * b3;
            acc[3][0] += a3 * b0; acc[3][1] += a3 * b1; acc[3][2] += a3 * b2; acc[3][3] += a3 * b3;
        }
        __syncthreads();
    }
    #pragma unroll
    for (int i = 0; i < 4; i++) {
        int r = rowBase + tm * 4 + i;
        #pragma unroll
        for (int j = 0; j < 4; j++) {
            int c = colBase + tn * 4 + j;
            float val = acc[i][j] + bias[c];
            if (RELU)   val = fmaxf(val, 0.f);
            if (RESADD) val += res[(size_t)r * J + c];
            C[(size_t)r * J + c] = val;
        }
    }
}

// ---------------- Flash attention (fp32, online softmax) -------------------
// grid: (S/64, H, B), 256 threads. BQ=64 queries, key tiles of 32.
__global__ __launch_bounds__(256) void flash_attn_kernel(
    const float* __restrict__ q, const float* __restrict__ k,
    const float* __restrict__ v, const int* __restrict__ mask,
    float* __restrict__ out)
{
    __shared__ float sQt[DDIM][64 + 1];   // [d][q]
    __shared__ float sKt[DDIM][32 + 1];   // [d][k]
    __shared__ float sV[32][64 + 1];      // [k][d]
    __shared__ float sP[64][32 + 1];      // [q][k]
    __shared__ float sRed[64][17];
    __shared__ float sM[64], sL[64], sScale[64];
    __shared__ int sMask[32];

    int tid = threadIdx.x;
    int tm = tid >> 4;        // 0..15 -> q rows tm*4..+3
    int tn = tid & 15;        // 0..15 -> k cols tn*2..+1 (S) / d cols tn*4..+3 (O)
    int q0 = blockIdx.x * 64;
    int h  = blockIdx.y;
    int b  = blockIdx.z;
    const float* qb = q + ((size_t)b * SS) * EE + h * DDIM;
    const float* kb = k + ((size_t)b * SS) * EE + h * DDIM;
    const float* vb = v + ((size_t)b * SS) * EE + h * DDIM;
    const int* mb = mask + (size_t)b * SS;   // mask is int32 (harness has no bool lane)

    #pragma unroll
    for (int i = 0; i < 16; i++) {
        int idx = tid + i * 256;          // 0..4095
        int r = idx >> 6, d = idx & 63;
        sQt[d][r] = qb[(size_t)(q0 + r) * EE + d];
    }
    if (tid < 64) { sM[tid] = -1e30f; sL[tid] = 0.f; }
    float acc[4][4];
    #pragma unroll
    for (int i = 0; i < 4; i++)
        #pragma unroll
        for (int j = 0; j < 4; j++) acc[i][j] = 0.f;
    __syncthreads();

    for (int kt = 0; kt < SS; kt += 32) {
        #pragma unroll
        for (int i = 0; i < 8; i++) {
            int idx = tid + i * 256;      // 0..2047
            int r = idx >> 6, d = idx & 63;
            float kvv = kb[(size_t)(kt + r) * EE + d];
            float vvv = vb[(size_t)(kt + r) * EE + d];
            sKt[d][r] = kvv;
            sV[r][d]  = vvv;
        }
        if (tid < 32) sMask[tid] = mb[kt + tid];
        __syncthreads();

        // S tile = Q K^T  (64q x 32k), microtile 4x2
        float sc[4][2];
        #pragma unroll
        for (int i = 0; i < 4; i++) { sc[i][0] = 0.f; sc[i][1] = 0.f; }
        #pragma unroll 8
        for (int d = 0; d < DDIM; d++) {
            float a0 = sQt[d][tm * 4 + 0], a1 = sQt[d][tm * 4 + 1];
            float a2 = sQt[d][tm * 4 + 2], a3 = sQt[d][tm * 4 + 3];
            float b0 = sKt[d][tn * 2 + 0], b1 = sKt[d][tn * 2 + 1];
            sc[0][0] += a0 * b0; sc[0][1] += a0 * b1;
            sc[1][0] += a1 * b0; sc[1][1] += a1 * b1;
            sc[2][0] += a2 * b0; sc[2][1] += a2 * b1;
            sc[3][0] += a3 * b0; sc[3][1] += a3 * b1;
        }
        bool mk0 = sMask[tn * 2 + 0] != 0;
        bool mk1 = sMask[tn * 2 + 1] != 0;
        #pragma unroll
        for (int i = 0; i < 4; i++) {
            sc[i][0] = mk0 ? -1e30f : sc[i][0] * 0.125f;
            sc[i][1] = mk1 ? -1e30f : sc[i][1] * 0.125f;
            sRed[tm * 4 + i][tn] = fmaxf(sc[i][0], sc[i][1]);
        }
        __syncthreads();
        if (tid < 64) {
            float m = sRed[tid][0];
            #pragma unroll
            for (int t2 = 1; t2 < 16; t2++) m = fmaxf(m, sRed[tid][t2]);
            float mo = sM[tid];
            float mn = fmaxf(mo, m);
            sM[tid]     = mn;
            sScale[tid] = __expf(mo - mn);
        }
        __syncthreads();
        // P = exp(S - m_new), row partial sums, rescale accumulator
        #pragma unroll
        for (int i = 0; i < 4; i++) {
            float mn = sM[tm * 4 + i];
            float p0 = mk0 ? 0.f : __expf(sc[i][0] - mn);
            float p1 = mk1 ? 0.f : __expf(sc[i][1] - mn);
            sP[tm * 4 + i][tn * 2 + 0] = p0;
            sP[tm * 4 + i][tn * 2 + 1] = p1;
            sRed[tm * 4 + i][tn] = p0 + p1;
            float scl = sScale[tm * 4 + i];
            #pragma unroll
            for (int j = 0; j < 4; j++) acc[i][j] *= scl;
        }
        __syncthreads();
        if (tid < 64) {
            float l = 0.f;
            #pragma unroll
            for (int t2 = 0; t2 < 16; t2++) l += sRed[tid][t2];
            sL[tid] = sL[tid] * sScale[tid] + l;
        }
        // O += P V  (64q x 64d), microtile 4x4
        #pragma unroll 8
        for (int kk = 0; kk < 32; kk++) {
            float a0 = sP[tm * 4 + 0][kk], a1 = sP[tm * 4 + 1][kk];
            float a2 = sP[tm * 4 + 2][kk], a3 = sP[tm * 4 + 3][kk];
            float b0 = sV[kk][tn * 4 + 0], b1 = sV[kk][tn * 4 + 1];
            float b2 = sV[kk][tn * 4 + 2], b3 = sV[kk][tn * 4 + 3];
            acc[0][0] += a0 * b0; acc[0][1] += a0 * b1; acc[0][2] += a0 * b2; acc[0][3] += a0 * b3;
            acc[1][0] += a1 * b0; acc[1][1] += a1 * b1; acc[1][2] += a1 * b2; acc[1][3] += a1 * b3;
            acc[2][0] += a2 * b0; acc[2][1] += a2 * b1; acc[2][2] += a2 * b2; acc[2][3] += a2 * b3;
            acc[3][0] += a3 * b0; acc[3][1] += a3 * b1; acc[3][2] += a3 * b2; acc[3][3] += a3 * b3;
        }
        __syncthreads();
    }
    #pragma unroll
    for (int i = 0; i < 4; i++) {
        float inv = 1.f / sL[tm * 4 + i];
        int row = b * SS + q0 + tm * 4 + i;
        #pragma unroll
        for (int j = 0; j < 4; j++)
            out[(size_t)row * EE + h * DDIM + tn * 4 + j] = acc[i][j] * inv;
    }
}

// ---------------- misc ------------------------------------------------------
__global__ void copy_f4(const float4* __restrict__ in, float4* __restrict__ out, int n4) {
    int i = blockIdx.x * blockDim.x + threadIdx.x;
    if (i < n4) out[i] = in[i];
}

// ---------------- launch ----------------------------------------------------
extern "C" void kernel_launch(void* const* d_in, const int* in_sizes, int n_in,
                              void* d_out, int out_size) {
    const float* x_in = (const float*)d_in[0];
    const int* mask = (const int*)d_in[1];   // bool serialized as int32 by harness
    const float* wq = (const float*)d_in[2];
    const float* bq = (const float*)d_in[3];
    const float* wk = (const float*)d_in[4];
    const float* bk = (const float*)d_in[5];
    const float* wv = (const float*)d_in[6];
    const float* bv = (const float*)d_in[7];
    const float* g1 = (const float*)d_in[8];
    const float* b1 = (const float*)d_in[9];
    const float* g2 = (const float*)d_in[10];
    const float* b2 = (const float*)d_in[11];
    const float* gf = (const float*)d_in[12];
    const float* bf = (const float*)d_in[13];
    const float* W1 = (const float*)d_in[14];
    const float* B1 = (const float*)d_in[15];
    const float* W2 = (const float*)d_in[16];
    const float* B2 = (const float*)d_in[17];
    float* outp = (float*)d_out;

    float *px, *ph, *pq, *pk, *pv, *pattn, *pffn;
    cudaGetSymbolAddress((void**)&px,    g_x);
    cudaGetSymbolAddress((void**)&ph,    g_h);
    cudaGetSymbolAddress((void**)&pq,    g_q);
    cudaGetSymbolAddress((void**)&pk,    g_k);
    cudaGetSymbolAddress((void**)&pv,    g_v);
    cudaGetSymbolAddress((void**)&pattn, g_attn);
    cudaGetSymbolAddress((void**)&pffn,  g_ffn);

    // x = input
    {
        int n4 = NROWS * EE / 4;
        copy_f4<<<(n4 + 255) / 256, 256>>>((const float4*)x_in, (float4*)px, n4);
    }

    dim3 gQKV(EE / 64, NROWS / 64);     // (8, 64)
    dim3 gFF1(DFFN / 64, NROWS / 64);   // (32, 64)
    dim3 gFF2(EE / 64, NROWS / 64);     // (8, 64)
    dim3 gAtt(SS / 64, HH, BB);         // (32, 8, 2)

    for (int l = 0; l < NLAYERS; l++) {
        const float* wql = wq + (size_t)l * EE * EE;
        const float* wkl = wk + (size_t)l * EE * EE;
        const float* wvl = wv + (size_t)l * EE * EE;
        const float* bql = bq + (size_t)l * EE;
        const float* bkl = bk + (size_t)l * EE;
        const float* bvl = bv + (size_t)l * EE;

        ln_kernel<1><<<NROWS, 128>>>(px, ph, g1, b1);
        gemm_nt<0, 0><<<gQKV, 256>>>(ph, wql, bql, pq, EE, EE, nullptr);
        gemm_nt<0, 0><<<gQKV, 256>>>(ph, wkl, bkl, pk, EE, EE, nullptr);
        gemm_nt<0, 0><<<gQKV, 256>>>(ph, wvl, bvl, pv, EE, EE, nullptr);
        flash_attn_kernel<<<gAtt, 256>>>(pq, pk, pv, mask, pattn);
        fuse_attn_res_ln<<<NROWS, 128>>>(pattn, px, ph, g2, b2);
        gemm_nt<1, 0><<<gFF1, 256>>>(ph, W1, B1, pffn, EE, DFFN, nullptr);
        gemm_nt<0, 1><<<gFF2, 256>>>(pffn, W2, B2, px, DFFN, EE, px);
    }
    ln_kernel<1><<<NROWS, 128>>>(px, outp, gf, bf);
}

// round 5
// speedup vs baseline: 1.4870x; 1.4870x over previous
#include <cuda_runtime.h>

#define BB      2
#define SS      2048
#define EE      512
#define HH      8
#define DDIM    64
#define NLAYERS 2
#define DFFN    2048
#define NROWS   4096   // BB*SS

// ---------------- scratch (device globals; no allocation allowed) ----------
__device__ float g_x[NROWS * EE];
__device__ float g_h[NROWS * EE];
__device__ float g_q[NROWS * EE];
__device__ float g_k[NROWS * EE];
__device__ float g_v[NROWS * EE];
__device__ float g_attn[NROWS * EE];
__device__ float g_ffn[NROWS * DFFN];

// ---------------- helpers ---------------------------------------------------
__device__ __forceinline__ void block_reduce2(float& s, float& s2) {
    __shared__ float shm[8];
    #pragma unroll
    for (int o = 16; o > 0; o >>= 1) {
        s  += __shfl_down_sync(0xffffffffu, s,  o);
        s2 += __shfl_down_sync(0xffffffffu, s2, o);
    }
    int w = threadIdx.x >> 5;
    __syncthreads();
    if ((threadIdx.x & 31) == 0) { shm[w] = s; shm[4 + w] = s2; }
    __syncthreads();
    s  = shm[0] + shm[1] + shm[2] + shm[3];
    s2 = shm[4] + shm[5] + shm[6] + shm[7];
}

// ---------------- LayerNorm (one block / row, 128 threads, E=512) ----------
template <int AFFINE>
__global__ void ln_kernel(const float* __restrict__ in, float* __restrict__ outp,
                          const float* __restrict__ g, const float* __restrict__ b) {
    int row = blockIdx.x;
    int t = threadIdx.x;
    const float* xr = in + (size_t)row * EE;
    float v[4];
    float s = 0.f, s2 = 0.f;
    #pragma unroll
    for (int i = 0; i < 4; i++) {
        v[i] = xr[t + i * 128];
        s += v[i]; s2 += v[i] * v[i];
    }
    block_reduce2(s, s2);
    float mu  = s * (1.f / EE);
    float var = s2 * (1.f / EE) - mu * mu;
    float r   = rsqrtf(var + 1e-5f);
    #pragma unroll
    for (int i = 0; i < 4; i++) {
        int idx = t + i * 128;
        float y = (v[i] - mu) * r;
        if (AFFINE) y = y * g[idx] + b[idx];
        outp[(size_t)row * EE + idx] = y;
    }
}

// -------- fused: x += LN(attn)*g2+b2 ; h = LN_noaffine(x) -------------------
__global__ void fuse_attn_res_ln(const float* __restrict__ attn, float* x,
                                 float* __restrict__ h,
                                 const float* __restrict__ g2,
                                 const float* __restrict__ b2) {
    int row = blockIdx.x;
    int t = threadIdx.x;
    const float* ar = attn + (size_t)row * EE;
    float a[4];
    float s = 0.f, s2 = 0.f;
    #pragma unroll
    for (int i = 0; i < 4; i++) {
        a[i] = ar[t + i * 128];
        s += a[i]; s2 += a[i] * a[i];
    }
    block_reduce2(s, s2);
    float mu  = s * (1.f / EE);
    float var = s2 * (1.f / EE) - mu * mu;
    float r   = rsqrtf(var + 1e-5f);

    float xv[4];
    s = 0.f; s2 = 0.f;
    #pragma unroll
    for (int i = 0; i < 4; i++) {
        int idx = t + i * 128;
        float y = (a[i] - mu) * r * g2[idx] + b2[idx];
        float xn = x[(size_t)row * EE + idx] + y;
        x[(size_t)row * EE + idx] = xn;
        xv[i] = xn;
        s += xn; s2 += xn * xn;
    }
    block_reduce2(s, s2);
    float mu2  = s * (1.f / EE);
    float var2 = s2 * (1.f / EE) - mu2 * mu2;
    float r2   = rsqrtf(var2 + 1e-5f);
    #pragma unroll
    for (int i = 0; i < 4; i++) {
        int idx = t + i * 128;
        h[(size_t)row * EE + idx] = (xv[i] - mu2) * r2;
    }
}

// ---------------- SGEMM body: C[n,j] = A[n,:].W[j,:] + bias[j] --------------
// 128x128 tile, K-step 16, 256 threads, 8x8 microtile (2x(4+4) split),
// double-buffered smem, float4 gmem loads, LDS.128 conflict-free reads.
template <int RELU, int RESADD>
__device__ __forceinline__ void gemm_body(
    const float* __restrict__ A, const float* __restrict__ W,
    const float* __restrict__ bias, float* __restrict__ C,
    int K, int J, const float* __restrict__ res,
    int rowBase, int colBase)
{
    __shared__ float sA[2][16][132];
    __shared__ float sB[2][16][132];
    int tid = threadIdx.x;
    int tx = tid & 15;        // 0..15 -> cols tx*4 and 64+tx*4
    int ty = tid >> 4;        // 0..15 -> rows ty*4 and 64+ty*4
    int lr = tid >> 2;        // 0..63 loader row (and +64)
    int lc = (tid & 3) << 2;  // loader col group 0,4,8,12

    const float* Ap = A + (size_t)(rowBase + lr) * K + lc;
    const float* Bp = W + (size_t)(colBase + lr) * K + lc;

    float acc[8][8];
    #pragma unroll
    for (int i = 0; i < 8; i++)
        #pragma unroll
        for (int j = 0; j < 8; j++) acc[i][j] = 0.f;

    float4 av[2], bv[2];
    // preload tile 0
    #pragma unroll
    for (int i = 0; i < 2; i++) {
        av[i] = *(const float4*)(Ap + (size_t)i * 64 * K);
        bv[i] = *(const float4*)(Bp + (size_t)i * 64 * K);
    }
    #pragma unroll
    for (int i = 0; i < 2; i++) {
        int r = lr + i * 64;
        sA[0][lc + 0][r] = av[i].x; sA[0][lc + 1][r] = av[i].y;
        sA[0][lc + 2][r] = av[i].z; sA[0][lc + 3][r] = av[i].w;
        sB[0][lc + 0][r] = bv[i].x; sB[0][lc + 1][r] = bv[i].y;
        sB[0][lc + 2][r] = bv[i].z; sB[0][lc + 3][r] = bv[i].w;
    }
    __syncthreads();

    int T = K >> 4;
    for (int t = 0; t < T; t++) {
        int buf = t & 1;
        if (t + 1 < T) {
            const float* Ap2 = Ap + (t + 1) * 16;
            const float* Bp2 = Bp + (t + 1) * 16;
            #pragma unroll
            for (int i = 0; i < 2; i++) {
                av[i] = *(const float4*)(Ap2 + (size_t)i * 64 * K);
                bv[i] = *(const float4*)(Bp2 + (size_t)i * 64 * K);
            }
        }
        #pragma unroll
        for (int kk = 0; kk < 16; kk++) {
            float4 a0 = *(const float4*)&sA[buf][kk][ty * 4];
            float4 a1 = *(const float4*)&sA[buf][kk][64 + ty * 4];
            float4 b0 = *(const float4*)&sB[buf][kk][tx * 4];
            float4 b1 = *(const float4*)&sB[buf][kk][64 + tx * 4];
            float aa[8] = {a0.x, a0.y, a0.z, a0.w, a1.x, a1.y, a1.z, a1.w};
            float bb[8] = {b0.x, b0.y, b0.z, b0.w, b1.x, b1.y, b1.z, b1.w};
            #pragma unroll
            for (int i = 0; i < 8; i++)
                #pragma unroll
                for (int j = 0; j < 8; j++)
                    acc[i][j] += aa[i] * bb[j];
        }
        if (t + 1 < T) {
            int nb = buf ^ 1;
            #pragma unroll
            for (int i = 0; i < 2; i++) {
                int r = lr + i * 64;
                sA[nb][lc + 0][r] = av[i].x; sA[nb][lc + 1][r] = av[i].y;
                sA[nb][lc + 2][r] = av[i].z; sA[nb][lc + 3][r] = av[i].w;
                sB[nb][lc + 0][r] = bv[i].x; sB[nb][lc + 1][r] = bv[i].y;
                sB[nb][lc + 2][r] = bv[i].z; sB[nb][lc + 3][r] = bv[i].w;
            }
            __syncthreads();
        }
    }

    // epilogue: 8 rows x 2 float4 cols
    #pragma unroll
    for (int ii = 0; ii < 2; ii++) {
        #pragma unroll
        for (int i = 0; i < 4; i++) {
            int r = rowBase + ii * 64 + ty * 4 + i;
            #pragma unroll
            for (int jj = 0; jj < 2; jj++) {
                int c = colBase + jj * 64 + tx * 4;
                float4 v;
                v.x = acc[ii * 4 + i][jj * 4 + 0] + bias[c + 0];
                v.y = acc[ii * 4 + i][jj * 4 + 1] + bias[c + 1];
                v.z = acc[ii * 4 + i][jj * 4 + 2] + bias[c + 2];
                v.w = acc[ii * 4 + i][jj * 4 + 3] + bias[c + 3];
                if (RELU) {
                    v.x = fmaxf(v.x, 0.f); v.y = fmaxf(v.y, 0.f);
                    v.z = fmaxf(v.z, 0.f); v.w = fmaxf(v.w, 0.f);
                }
                if (RESADD) {
                    const float4 rv = *(const float4*)&res[(size_t)r * J + c];
                    v.x += rv.x; v.y += rv.y; v.z += rv.z; v.w += rv.w;
                }
                *(float4*)&C[(size_t)r * J + c] = v;
            }
        }
    }
}

template <int RELU, int RESADD>
__global__ __launch_bounds__(256, 2) void gemm_nt(
    const float* __restrict__ A, const float* __restrict__ W,
    const float* __restrict__ bias, float* __restrict__ C,
    int K, int J, const float* __restrict__ res)
{
    gemm_body<RELU, RESADD>(A, W, bias, C, K, J, res,
                            blockIdx.y * 128, blockIdx.x * 128);
}

// fused QKV: blockIdx.z selects which projection, 3x blocks in one launch
__global__ __launch_bounds__(256, 2) void gemm_qkv(
    const float* __restrict__ A,
    const float* __restrict__ wq, const float* __restrict__ wk, const float* __restrict__ wv,
    const float* __restrict__ bq, const float* __restrict__ bk, const float* __restrict__ bv,
    float* __restrict__ q, float* __restrict__ k, float* __restrict__ v)
{
    const float* W  = (blockIdx.z == 0) ? wq : (blockIdx.z == 1) ? wk : wv;
    const float* bi = (blockIdx.z == 0) ? bq : (blockIdx.z == 1) ? bk : bv;
    float*       C  = (blockIdx.z == 0) ? q  : (blockIdx.z == 1) ? k  : v;
    gemm_body<0, 0>(A, W, bi, C, EE, EE, nullptr,
                    blockIdx.y * 128, blockIdx.x * 128);
}

// ---------------- Flash attention (fp32, online softmax) -------------------
// grid: (S/64, H, B), 256 threads. BQ=64 queries, key tiles of 32.
__global__ __launch_bounds__(256) void flash_attn_kernel(
    const float* __restrict__ q, const float* __restrict__ k,
    const float* __restrict__ v, const int* __restrict__ mask,
    float* __restrict__ out)
{
    __shared__ float sQt[DDIM][64 + 1];   // [d][q]
    __shared__ float sKt[DDIM][32 + 1];   // [d][k]
    __shared__ float sV[32][64 + 1];      // [k][d]
    __shared__ float sP[64][32 + 1];      // [q][k]
    __shared__ float sRed[64][17];
    __shared__ float sM[64], sL[64], sScale[64];
    __shared__ int sMask[32];

    int tid = threadIdx.x;
    int tm = tid >> 4;        // 0..15 -> q rows tm*4..+3
    int tn = tid & 15;        // 0..15 -> k cols tn*2..+1 (S) / d cols tn*4..+3 (O)
    int q0 = blockIdx.x * 64;
    int h  = blockIdx.y;
    int b  = blockIdx.z;
    const float* qb = q + ((size_t)b * SS) * EE + h * DDIM;
    const float* kb = k + ((size_t)b * SS) * EE + h * DDIM;
    const float* vb = v + ((size_t)b * SS) * EE + h * DDIM;
    const int* mb = mask + (size_t)b * SS;   // mask is int32

    #pragma unroll
    for (int i = 0; i < 16; i++) {
        int idx = tid + i * 256;          // 0..4095
        int r = idx >> 6, d = idx & 63;
        sQt[d][r] = qb[(size_t)(q0 + r) * EE + d];
    }
    if (tid < 64) { sM[tid] = -1e30f; sL[tid] = 0.f; }
    float acc[4][4];
    #pragma unroll
    for (int i = 0; i < 4; i++)
        #pragma unroll
        for (int j = 0; j < 4; j++) acc[i][j] = 0.f;
    __syncthreads();

    for (int kt = 0; kt < SS; kt += 32) {
        #pragma unroll
        for (int i = 0; i < 8; i++) {
            int idx = tid + i * 256;      // 0..2047
            int r = idx >> 6, d = idx & 63;
            float kvv = kb[(size_t)(kt + r) * EE + d];
            float vvv = vb[(size_t)(kt + r) * EE + d];
            sKt[d][r] = kvv;
            sV[r][d]  = vvv;
        }
        if (tid < 32) sMask[tid] = mb[kt + tid];
        __syncthreads();

        // S tile = Q K^T  (64q x 32k), microtile 4x2
        float sc[4][2];
        #pragma unroll
        for (int i = 0; i < 4; i++) { sc[i][0] = 0.f; sc[i][1] = 0.f; }
        #pragma unroll 8
        for (int d = 0; d < DDIM; d++) {
            float a0 = sQt[d][tm * 4 + 0], a1 = sQt[d][tm * 4 + 1];
            float a2 = sQt[d][tm * 4 + 2], a3 = sQt[d][tm * 4 + 3];
            float b0 = sKt[d][tn * 2 + 0], b1 = sKt[d][tn * 2 + 1];
            sc[0][0] += a0 * b0; sc[0][1] += a0 * b1;
            sc[1][0] += a1 * b0; sc[1][1] += a1 * b1;
            sc[2][0] += a2 * b0; sc[2][1] += a2 * b1;
            sc[3][0] += a3 * b0; sc[3][1] += a3 * b1;
        }
        bool mk0 = sMask[tn * 2 + 0] != 0;
        bool mk1 = sMask[tn * 2 + 1] != 0;
        #pragma unroll
        for (int i = 0; i < 4; i++) {
            sc[i][0] = mk0 ? -1e30f : sc[i][0] * 0.125f;
            sc[i][1] = mk1 ? -1e30f : sc[i][1] * 0.125f;
            sRed[tm * 4 + i][tn] = fmaxf(sc[i][0], sc[i][1]);
        }
        __syncthreads();
        if (tid < 64) {
            float m = sRed[tid][0];
            #pragma unroll
            for (int t2 = 1; t2 < 16; t2++) m = fmaxf(m, sRed[tid][t2]);
            float mo = sM[tid];
            float mn = fmaxf(mo, m);
            sM[tid]     = mn;
            sScale[tid] = __expf(mo - mn);
        }
        __syncthreads();
        #pragma unroll
        for (int i = 0; i < 4; i++) {
            float mn = sM[tm * 4 + i];
            float p0 = mk0 ? 0.f : __expf(sc[i][0] - mn);
            float p1 = mk1 ? 0.f : __expf(sc[i][1] - mn);
            sP[tm * 4 + i][tn * 2 + 0] = p0;
            sP[tm * 4 + i][tn * 2 + 1] = p1;
            sRed[tm * 4 + i][tn] = p0 + p1;
            float scl = sScale[tm * 4 + i];
            #pragma unroll
            for (int j = 0; j < 4; j++) acc[i][j] *= scl;
        }
        __syncthreads();
        if (tid < 64) {
            float l = 0.f;
            #pragma unroll
            for (int t2 = 0; t2 < 16; t2++) l += sRed[tid][t2];
            sL[tid] = sL[tid] * sScale[tid] + l;
        }
        // O += P V  (64q x 64d), microtile 4x4
        #pragma unroll 8
        for (int kk = 0; kk < 32; kk++) {
            float a0 = sP[tm * 4 + 0][kk], a1 = sP[tm * 4 + 1][kk];
            float a2 = sP[tm * 4 + 2][kk], a3 = sP[tm * 4 + 3][kk];
            float b0 = sV[kk][tn * 4 + 0], b1 = sV[kk][tn * 4 + 1];
            float b2 = sV[kk][tn * 4 + 2], b3 = sV[kk][tn * 4 + 3];
            acc[0][0] += a0 * b0; acc[0][1] += a0 * b1; acc[0][2] += a0 * b2; acc[0][3] += a0 * b3;
            acc[1][0] += a1 * b0; acc[1][1] += a1 * b1; acc[1][2] += a1 * b2; acc[1][3] += a1 * b3;
            acc[2][0] += a2 * b0; acc[2][1] += a2 * b1; acc[2][2] += a2 * b2; acc[2][3] += a2 * b3;
            acc[3][0] += a3 * b0; acc[3][1] += a3 * b1; acc[3][2] += a3 * b2; acc[3][3] += a3 * b3;
        }
        __syncthreads();
    }
    #pragma unroll
    for (int i = 0; i < 4; i++) {
        float inv = 1.f / sL[tm * 4 + i];
        int row = b * SS + q0 + tm * 4 + i;
        #pragma unroll
        for (int j = 0; j < 4; j++)
            out[(size_t)row * EE + h * DDIM + tn * 4 + j] = acc[i][j] * inv;
    }
}

// ---------------- misc ------------------------------------------------------
__global__ void copy_f4(const float4* __restrict__ in, float4* __restrict__ out, int n4) {
    int i = blockIdx.x * blockDim.x + threadIdx.x;
    if (i < n4) out[i] = in[i];
}

// ---------------- launch ----------------------------------------------------
extern "C" void kernel_launch(void* const* d_in, const int* in_sizes, int n_in,
                              void* d_out, int out_size) {
    const float* x_in = (const float*)d_in[0];
    const int* mask = (const int*)d_in[1];
    const float* wq = (const float*)d_in[2];
    const float* bq = (const float*)d_in[3];
    const float* wk = (const float*)d_in[4];
    const float* bk = (const float*)d_in[5];
    const float* wv = (const float*)d_in[6];
    const float* bv = (const float*)d_in[7];
    const float* g1 = (const float*)d_in[8];
    const float* b1 = (const float*)d_in[9];
    const float* g2 = (const float*)d_in[10];
    const float* b2 = (const float*)d_in[11];
    const float* gf = (const float*)d_in[12];
    const float* bf = (const float*)d_in[13];
    const float* W1 = (const float*)d_in[14];
    const float* B1 = (const float*)d_in[15];
    const float* W2 = (const float*)d_in[16];
    const float* B2 = (const float*)d_in[17];
    float* outp = (float*)d_out;

    float *px, *ph, *pq, *pk, *pv, *pattn, *pffn;
    cudaGetSymbolAddress((void**)&px,    g_x);
    cudaGetSymbolAddress((void**)&ph,    g_h);
    cudaGetSymbolAddress((void**)&pq,    g_q);
    cudaGetSymbolAddress((void**)&pk,    g_k);
    cudaGetSymbolAddress((void**)&pv,    g_v);
    cudaGetSymbolAddress((void**)&pattn, g_attn);
    cudaGetSymbolAddress((void**)&pffn,  g_ffn);

    {
        int n4 = NROWS * EE / 4;
        copy_f4<<<(n4 + 255) / 256, 256>>>((const float4*)x_in, (float4*)px, n4);
    }

    dim3 gQKV(EE / 128, NROWS / 128, 3);   // (4, 32, 3)
    dim3 gFF1(DFFN / 128, NROWS / 128);    // (16, 32)
    dim3 gFF2(EE / 128, NROWS / 128);      // (4, 32)
    dim3 gAtt(SS / 64, HH, BB);            // (32, 8, 2)

    for (int l = 0; l < NLAYERS; l++) {
        const float* wql = wq + (size_t)l * EE * EE;
        const float* wkl = wk + (size_t)l * EE * EE;
        const float* wvl = wv + (size_t)l * EE * EE;
        const float* bql = bq + (size_t)l * EE;
        const float* bkl = bk + (size_t)l * EE;
        const float* bvl = bv + (size_t)l * EE;

        ln_kernel<1><<<NROWS, 128>>>(px, ph, g1, b1);
        gemm_qkv<<<gQKV, 256>>>(ph, wql, wkl, wvl, bql, bkl, bvl, pq, pk, pv);
        flash_attn_kernel<<<gAtt, 256>>>(pq, pk, pv, mask, pattn);
        fuse_attn_res_ln<<<NROWS, 128>>>(pattn, px, ph, g2, b2);
        gemm_nt<1, 0><<<gFF1, 256>>>(ph, W1, B1, pffn, EE, DFFN, nullptr);
        gemm_nt<0, 1><<<gFF2, 256>>>(pffn, W2, B2, px, DFFN, EE, px);
    }
    ln_kernel<1><<<NROWS, 128>>>(px, outp, gf, bf);
}

// round 6
// speedup vs baseline: 1.7623x; 1.1852x over previous
#include <cuda_runtime.h>

#define BB      2
#define SS      2048
#define EE      512
#define HH      8
#define DDIM    64
#define NLAYERS 2
#define DFFN    2048
#define NROWS   4096   // BB*SS

#define BQ      128
#define BK      64
// dynamic smem floats: Qt 64*(BQ+4) + Kt 64*(BK+4) + V BK*68 + P BQ*68 + Red BQ*17 + M/L/Scale 3*BQ
#define FA_SMEM_FLOATS (64*(BQ+4) + 64*(BK+4) + BK*68 + BQ*68 + BQ*17 + 3*BQ)
#define FA_SMEM_BYTES  (FA_SMEM_FLOATS*4 + BK*4)

// ---------------- scratch (device globals; no allocation allowed) ----------
__device__ float g_x[NROWS * EE];
__device__ float g_h[NROWS * EE];
__device__ float g_q[NROWS * EE];
__device__ float g_k[NROWS * EE];
__device__ float g_v[NROWS * EE];
__device__ float g_attn[NROWS * EE];
__device__ float g_ffn[NROWS * DFFN];

// ---------------- helpers ---------------------------------------------------
__device__ __forceinline__ void block_reduce2(float& s, float& s2) {
    __shared__ float shm[8];
    #pragma unroll
    for (int o = 16; o > 0; o >>= 1) {
        s  += __shfl_down_sync(0xffffffffu, s,  o);
        s2 += __shfl_down_sync(0xffffffffu, s2, o);
    }
    int w = threadIdx.x >> 5;
    __syncthreads();
    if ((threadIdx.x & 31) == 0) { shm[w] = s; shm[4 + w] = s2; }
    __syncthreads();
    s  = shm[0] + shm[1] + shm[2] + shm[3];
    s2 = shm[4] + shm[5] + shm[6] + shm[7];
}

// ---------------- LayerNorm (one block / row, 128 threads, E=512) ----------
template <int AFFINE>
__global__ void ln_kernel(const float* __restrict__ in, float* __restrict__ outp,
                          const float* __restrict__ g, const float* __restrict__ b) {
    int row = blockIdx.x;
    int t = threadIdx.x;
    const float* xr = in + (size_t)row * EE;
    float v[4];
    float s = 0.f, s2 = 0.f;
    #pragma unroll
    for (int i = 0; i < 4; i++) {
        v[i] = xr[t + i * 128];
        s += v[i]; s2 += v[i] * v[i];
    }
    block_reduce2(s, s2);
    float mu  = s * (1.f / EE);
    float var = s2 * (1.f / EE) - mu * mu;
    float r   = rsqrtf(var + 1e-5f);
    #pragma unroll
    for (int i = 0; i < 4; i++) {
        int idx = t + i * 128;
        float y = (v[i] - mu) * r;
        if (AFFINE) y = y * g[idx] + b[idx];
        outp[(size_t)row * EE + idx] = y;
    }
}

// -------- fused: x += LN(attn)*g2+b2 ; h = LN_noaffine(x) -------------------
__global__ void fuse_attn_res_ln(const float* __restrict__ attn, float* x,
                                 float* __restrict__ h,
                                 const float* __restrict__ g2,
                                 const float* __restrict__ b2) {
    int row = blockIdx.x;
    int t = threadIdx.x;
    const float* ar = attn + (size_t)row * EE;
    float a[4];
    float s = 0.f, s2 = 0.f;
    #pragma unroll
    for (int i = 0; i < 4; i++) {
        a[i] = ar[t + i * 128];
        s += a[i]; s2 += a[i] * a[i];
    }
    block_reduce2(s, s2);
    float mu  = s * (1.f / EE);
    float var = s2 * (1.f / EE) - mu * mu;
    float r   = rsqrtf(var + 1e-5f);

    float xv[4];
    s = 0.f; s2 = 0.f;
    #pragma unroll
    for (int i = 0; i < 4; i++) {
        int idx = t + i * 128;
        float y = (a[i] - mu) * r * g2[idx] + b2[idx];
        float xn = x[(size_t)row * EE + idx] + y;
        x[(size_t)row * EE + idx] = xn;
        xv[i] = xn;
        s += xn; s2 += xn * xn;
    }
    block_reduce2(s, s2);
    float mu2  = s * (1.f / EE);
    float var2 = s2 * (1.f / EE) - mu2 * mu2;
    float r2   = rsqrtf(var2 + 1e-5f);
    #pragma unroll
    for (int i = 0; i < 4; i++) {
        int idx = t + i * 128;
        h[(size_t)row * EE + idx] = (xv[i] - mu2) * r2;
    }
}

// ---------------- SGEMM body: C[n,j] = A[n,:].W[j,:] + bias[j] --------------
template <int RELU, int RESADD>
__device__ __forceinline__ void gemm_body(
    const float* __restrict__ A, const float* __restrict__ W,
    const float* __restrict__ bias, float* __restrict__ C,
    int K, int J, const float* __restrict__ res,
    int rowBase, int colBase)
{
    __shared__ float sA[2][16][132];
    __shared__ float sB[2][16][132];
    int tid = threadIdx.x;
    int tx = tid & 15;
    int ty = tid >> 4;
    int lr = tid >> 2;
    int lc = (tid & 3) << 2;

    const float* Ap = A + (size_t)(rowBase + lr) * K + lc;
    const float* Bp = W + (size_t)(colBase + lr) * K + lc;

    float acc[8][8];
    #pragma unroll
    for (int i = 0; i < 8; i++)
        #pragma unroll
        for (int j = 0; j < 8; j++) acc[i][j] = 0.f;

    float4 av[2], bv[2];
    #pragma unroll
    for (int i = 0; i < 2; i++) {
        av[i] = *(const float4*)(Ap + (size_t)i * 64 * K);
        bv[i] = *(const float4*)(Bp + (size_t)i * 64 * K);
    }
    #pragma unroll
    for (int i = 0; i < 2; i++) {
        int r = lr + i * 64;
        sA[0][lc + 0][r] = av[i].x; sA[0][lc + 1][r] = av[i].y;
        sA[0][lc + 2][r] = av[i].z; sA[0][lc + 3][r] = av[i].w;
        sB[0][lc + 0][r] = bv[i].x; sB[0][lc + 1][r] = bv[i].y;
        sB[0][lc + 2][r] = bv[i].z; sB[0][lc + 3][r] = bv[i].w;
    }
    __syncthreads();

    int T = K >> 4;
    for (int t = 0; t < T; t++) {
        int buf = t & 1;
        if (t + 1 < T) {
            const float* Ap2 = Ap + (t + 1) * 16;
            const float* Bp2 = Bp + (t + 1) * 16;
            #pragma unroll
            for (int i = 0; i < 2; i++) {
                av[i] = *(const float4*)(Ap2 + (size_t)i * 64 * K);
                bv[i] = *(const float4*)(Bp2 + (size_t)i * 64 * K);
            }
        }
        #pragma unroll
        for (int kk = 0; kk < 16; kk++) {
            float4 a0 = *(const float4*)&sA[buf][kk][ty * 4];
            float4 a1 = *(const float4*)&sA[buf][kk][64 + ty * 4];
            float4 b0 = *(const float4*)&sB[buf][kk][tx * 4];
            float4 b1 = *(const float4*)&sB[buf][kk][64 + tx * 4];
            float aa[8] = {a0.x, a0.y, a0.z, a0.w, a1.x, a1.y, a1.z, a1.w};
            float bb[8] = {b0.x, b0.y, b0.z, b0.w, b1.x, b1.y, b1.z, b1.w};
            #pragma unroll
            for (int i = 0; i < 8; i++)
                #pragma unroll
                for (int j = 0; j < 8; j++)
                    acc[i][j] += aa[i] * bb[j];
        }
        if (t + 1 < T) {
            int nb = buf ^ 1;
            #pragma unroll
            for (int i = 0; i < 2; i++) {
                int r = lr + i * 64;
                sA[nb][lc + 0][r] = av[i].x; sA[nb][lc + 1][r] = av[i].y;
                sA[nb][lc + 2][r] = av[i].z; sA[nb][lc + 3][r] = av[i].w;
                sB[nb][lc + 0][r] = bv[i].x; sB[nb][lc + 1][r] = bv[i].y;
                sB[nb][lc + 2][r] = bv[i].z; sB[nb][lc + 3][r] = bv[i].w;
            }
            __syncthreads();
        }
    }

    #pragma unroll
    for (int ii = 0; ii < 2; ii++) {
        #pragma unroll
        for (int i = 0; i < 4; i++) {
            int r = rowBase + ii * 64 + ty * 4 + i;
            #pragma unroll
            for (int jj = 0; jj < 2; jj++) {
                int c = colBase + jj * 64 + tx * 4;
                float4 v;
                v.x = acc[ii * 4 + i][jj * 4 + 0] + bias[c + 0];
                v.y = acc[ii * 4 + i][jj * 4 + 1] + bias[c + 1];
                v.z = acc[ii * 4 + i][jj * 4 + 2] + bias[c + 2];
                v.w = acc[ii * 4 + i][jj * 4 + 3] + bias[c + 3];
                if (RELU) {
                    v.x = fmaxf(v.x, 0.f); v.y = fmaxf(v.y, 0.f);
                    v.z = fmaxf(v.z, 0.f); v.w = fmaxf(v.w, 0.f);
                }
                if (RESADD) {
                    const float4 rv = *(const float4*)&res[(size_t)r * J + c];
                    v.x += rv.x; v.y += rv.y; v.z += rv.z; v.w += rv.w;
                }
                *(float4*)&C[(size_t)r * J + c] = v;
            }
        }
    }
}

template <int RELU, int RESADD>
__global__ __launch_bounds__(256, 2) void gemm_nt(
    const float* __restrict__ A, const float* __restrict__ W,
    const float* __restrict__ bias, float* __restrict__ C,
    int K, int J, const float* __restrict__ res)
{
    gemm_body<RELU, RESADD>(A, W, bias, C, K, J, res,
                            blockIdx.y * 128, blockIdx.x * 128);
}

__global__ __launch_bounds__(256, 2) void gemm_qkv(
    const float* __restrict__ A,
    const float* __restrict__ wq, const float* __restrict__ wk, const float* __restrict__ wv,
    const float* __restrict__ bq, const float* __restrict__ bk, const float* __restrict__ bv,
    float* __restrict__ q, float* __restrict__ k, float* __restrict__ v)
{
    const float* W  = (blockIdx.z == 0) ? wq : (blockIdx.z == 1) ? wk : wv;
    const float* bi = (blockIdx.z == 0) ? bq : (blockIdx.z == 1) ? bk : bv;
    float*       C  = (blockIdx.z == 0) ? q  : (blockIdx.z == 1) ? k  : v;
    gemm_body<0, 0>(A, W, bi, C, EE, EE, nullptr,
                    blockIdx.y * 128, blockIdx.x * 128);
}

// ---------------- Flash attention v2: BQ=128, BK=64, 8x4 microtiles --------
// grid: (S/BQ, H, B), 256 threads, ~111KB dynamic smem, fully LDS.128.
__global__ __launch_bounds__(256, 1) void flash_attn_kernel(
    const float* __restrict__ q, const float* __restrict__ k,
    const float* __restrict__ v, const int* __restrict__ mask,
    float* __restrict__ out)
{
    extern __shared__ float sm[];
    float* sQt   = sm;                       // [64][BQ+4]  (d-major)
    float* sKt   = sQt + 64 * (BQ + 4);      // [64][BK+4]  (d-major)
    float* sV    = sKt + 64 * (BK + 4);      // [BK][68]    (k-major)
    float* sP    = sV + BK * 68;             // [BQ][68]
    float* sRed  = sP + BQ * 68;             // [BQ][17]
    float* sM    = sRed + BQ * 17;
    float* sL    = sM + BQ;
    float* sScl  = sL + BQ;
    int*   sMask = (int*)(sScl + BQ);

    int tid = threadIdx.x;
    int tx = tid & 15;        // k/d group: cols tx*4..+3
    int ty = tid >> 4;        // q group: rows ty*4..+3 and 64+ty*4..+3
    int q0 = blockIdx.x * BQ;
    int h  = blockIdx.y;
    int b  = blockIdx.z;
    const float* qb = q + ((size_t)b * SS) * EE + h * DDIM;
    const float* kb = k + ((size_t)b * SS) * EE + h * DDIM;
    const float* vb = v + ((size_t)b * SS) * EE + h * DDIM;
    const int*   mb = mask + (size_t)b * SS;

    int rows[8];
    #pragma unroll
    for (int i = 0; i < 8; i++) rows[i] = (i < 4) ? (ty * 4 + i) : (64 + ty * 4 + i - 4);

    // load Q (transposed to d-major)
    #pragma unroll
    for (int i = 0; i < 8; i++) {
        int g  = tid + i * 256;          // 0..2047 float4-groups
        int r  = g >> 4;                 // 0..127
        int d4 = (g & 15) << 2;
        float4 qv = *(const float4*)&qb[(size_t)(q0 + r) * EE + d4];
        sQt[(d4 + 0) * (BQ + 4) + r] = qv.x;
        sQt[(d4 + 1) * (BQ + 4) + r] = qv.y;
        sQt[(d4 + 2) * (BQ + 4) + r] = qv.z;
        sQt[(d4 + 3) * (BQ + 4) + r] = qv.w;
    }
    if (tid < BQ) { sM[tid] = -1e30f; sL[tid] = 0.f; }
    float accO[8][4];
    #pragma unroll
    for (int i = 0; i < 8; i++)
        #pragma unroll
        for (int j = 0; j < 4; j++) accO[i][j] = 0.f;
    __syncthreads();

    for (int kt = 0; kt < SS; kt += BK) {
        // load K (transposed) + V (direct)
        #pragma unroll
        for (int i = 0; i < 4; i++) {
            int g  = tid + i * 256;      // 0..1023
            int r  = g >> 4;             // 0..63
            int d4 = (g & 15) << 2;
            float4 kv = *(const float4*)&kb[(size_t)(kt + r) * EE + d4];
            sKt[(d4 + 0) * (BK + 4) + r] = kv.x;
            sKt[(d4 + 1) * (BK + 4) + r] = kv.y;
            sKt[(d4 + 2) * (BK + 4) + r] = kv.z;
            sKt[(d4 + 3) * (BK + 4) + r] = kv.w;
            float4 vv = *(const float4*)&vb[(size_t)(kt + r) * EE + d4];
            *(float4*)&sV[r * 68 + d4] = vv;
        }
        if (tid < BK) sMask[tid] = mb[kt + tid];
        __syncthreads();

        // S = Q K^T  (128q x 64k), microtile 8x4, LDS.128 only
        float accS[8][4];
        #pragma unroll
        for (int i = 0; i < 8; i++)
            #pragma unroll
            for (int j = 0; j < 4; j++) accS[i][j] = 0.f;
        #pragma unroll 8
        for (int d = 0; d < DDIM; d++) {
            float4 a0 = *(const float4*)&sQt[d * (BQ + 4) + ty * 4];
            float4 a1 = *(const float4*)&sQt[d * (BQ + 4) + 64 + ty * 4];
            float4 bv4 = *(const float4*)&sKt[d * (BK + 4) + tx * 4];
            float aa[8] = {a0.x, a0.y, a0.z, a0.w, a1.x, a1.y, a1.z, a1.w};
            #pragma unroll
            for (int i = 0; i < 8; i++) {
                accS[i][0] += aa[i] * bv4.x;
                accS[i][1] += aa[i] * bv4.y;
                accS[i][2] += aa[i] * bv4.z;
                accS[i][3] += aa[i] * bv4.w;
            }
        }
        int mk[4];
        #pragma unroll
        for (int j = 0; j < 4; j++) mk[j] = sMask[tx * 4 + j];
        // mask + scale + per-thread row max
        #pragma unroll
        for (int i = 0; i < 8; i++) {
            float m = -1e30f;
            #pragma unroll
            for (int j = 0; j < 4; j++) {
                accS[i][j] = mk[j] ? -1e30f : accS[i][j] * 0.125f;
                m = fmaxf(m, accS[i][j]);
            }
            sRed[rows[i] * 17 + tx] = m;
        }
        __syncthreads();
        if (tid < BQ) {
            float m = sRed[tid * 17];
            #pragma unroll
            for (int t2 = 1; t2 < 16; t2++) m = fmaxf(m, sRed[tid * 17 + t2]);
            float mo = sM[tid];
            float mn = fmaxf(mo, m);
            sM[tid]   = mn;
            sScl[tid] = __expf(mo - mn);
        }
        __syncthreads();
        // P = exp(S - m), partial sums, rescale accO
        #pragma unroll
        for (int i = 0; i < 8; i++) {
            int row = rows[i];
            float mn  = sM[row];
            float scl = sScl[row];
            float4 p;
            p.x = mk[0] ? 0.f : __expf(accS[i][0] - mn);
            p.y = mk[1] ? 0.f : __expf(accS[i][1] - mn);
            p.z = mk[2] ? 0.f : __expf(accS[i][2] - mn);
            p.w = mk[3] ? 0.f : __expf(accS[i][3] - mn);
            *(float4*)&sP[row * 68 + tx * 4] = p;
            sRed[row * 17 + tx] = p.x + p.y + p.z + p.w;
            #pragma unroll
            for (int j = 0; j < 4; j++) accO[i][j] *= scl;
        }
        __syncthreads();
        if (tid < BQ) {
            float l = 0.f;
            #pragma unroll
            for (int t2 = 0; t2 < 16; t2++) l += sRed[tid * 17 + t2];
            sL[tid] = sL[tid] * sScl[tid] + l;
        }
        // O += P V  (128q x 64d), k stepped by 4, LDS.128 only
        #pragma unroll 4
        for (int kk = 0; kk < BK; kk += 4) {
            float4 b0 = *(const float4*)&sV[(kk + 0) * 68 + tx * 4];
            float4 b1 = *(const float4*)&sV[(kk + 1) * 68 + tx * 4];
            float4 b2 = *(const float4*)&sV[(kk + 2) * 68 + tx * 4];
            float4 b3 = *(const float4*)&sV[(kk + 3) * 68 + tx * 4];
            #pragma unroll
            for (int i = 0; i < 8; i++) {
                float4 a = *(const float4*)&sP[rows[i] * 68 + kk];
                accO[i][0] += a.x * b0.x + a.y * b1.x + a.z * b2.x + a.w * b3.x;
                accO[i][1] += a.x * b0.y + a.y * b1.y + a.z * b2.y + a.w * b3.y;
                accO[i][2] += a.x * b0.z + a.y * b1.z + a.z * b2.z + a.w * b3.z;
                accO[i][3] += a.x * b0.w + a.y * b1.w + a.z * b2.w + a.w * b3.w;
            }
        }
        __syncthreads();
    }
    #pragma unroll
    for (int i = 0; i < 8; i++) {
        int row = rows[i];
        float inv = 1.f / sL[row];
        float4 o;
        o.x = accO[i][0] * inv; o.y = accO[i][1] * inv;
        o.z = accO[i][2] * inv; o.w = accO[i][3] * inv;
        *(float4*)&out[(size_t)(b * SS + q0 + row) * EE + h * DDIM + tx * 4] = o;
    }
}

// ---------------- misc ------------------------------------------------------
__global__ void copy_f4(const float4* __restrict__ in, float4* __restrict__ out, int n4) {
    int i = blockIdx.x * blockDim.x + threadIdx.x;
    if (i < n4) out[i] = in[i];
}

// ---------------- launch ----------------------------------------------------
extern "C" void kernel_launch(void* const* d_in, const int* in_sizes, int n_in,
                              void* d_out, int out_size) {
    const float* x_in = (const float*)d_in[0];
    const int* mask = (const int*)d_in[1];
    const float* wq = (const float*)d_in[2];
    const float* bq = (const float*)d_in[3];
    const float* wk = (const float*)d_in[4];
    const float* bk = (const float*)d_in[5];
    const float* wv = (const float*)d_in[6];
    const float* bv = (const float*)d_in[7];
    const float* g1 = (const float*)d_in[8];
    const float* b1 = (const float*)d_in[9];
    const float* g2 = (const float*)d_in[10];
    const float* b2 = (const float*)d_in[11];
    const float* gf = (const float*)d_in[12];
    const float* bf = (const float*)d_in[13];
    const float* W1 = (const float*)d_in[14];
    const float* B1 = (const float*)d_in[15];
    const float* W2 = (const float*)d_in[16];
    const float* B2 = (const float*)d_in[17];
    float* outp = (float*)d_out;

    float *px, *ph, *pq, *pk, *pv, *pattn, *pffn;
    cudaGetSymbolAddress((void**)&px,    g_x);
    cudaGetSymbolAddress((void**)&ph,    g_h);
    cudaGetSymbolAddress((void**)&pq,    g_q);
    cudaGetSymbolAddress((void**)&pk,    g_k);
    cudaGetSymbolAddress((void**)&pv,    g_v);
    cudaGetSymbolAddress((void**)&pattn, g_attn);
    cudaGetSymbolAddress((void**)&pffn,  g_ffn);

    static int smem_set = 0;
    if (!smem_set) {
        cudaFuncSetAttribute(flash_attn_kernel,
                             cudaFuncAttributeMaxDynamicSharedMemorySize, FA_SMEM_BYTES);
        smem_set = 1;
    }

    {
        int n4 = NROWS * EE / 4;
        copy_f4<<<(n4 + 255) / 256, 256>>>((const float4*)x_in, (float4*)px, n4);
    }

    dim3 gQKV(EE / 128, NROWS / 128, 3);   // (4, 32, 3)
    dim3 gFF1(DFFN / 128, NROWS / 128);    // (16, 32)
    dim3 gFF2(EE / 128, NROWS / 128);      // (4, 32)
    dim3 gAtt(SS / BQ, HH, BB);            // (16, 8, 2)

    for (int l = 0; l < NLAYERS; l++) {
        const float* wql = wq + (size_t)l * EE * EE;
        const float* wkl = wk + (size_t)l * EE * EE;
        const float* wvl = wv + (size_t)l * EE * EE;
        const float* bql = bq + (size_t)l * EE;
        const float* bkl = bk + (size_t)l * EE;
        const float* bvl = bv + (size_t)l * EE;

        ln_kernel<1><<<NROWS, 128>>>(px, ph, g1, b1);
        gemm_qkv<<<gQKV, 256>>>(ph, wql, wkl, wvl, bql, bkl, bvl, pq, pk, pv);
        flash_attn_kernel<<<gAtt, 256, FA_SMEM_BYTES>>>(pq, pk, pv, mask, pattn);
        fuse_attn_res_ln<<<NROWS, 128>>>(pattn, px, ph, g2, b2);
        gemm_nt<1, 0><<<gFF1, 256>>>(ph, W1, B1, pffn, EE, DFFN, nullptr);
        gemm_nt<0, 1><<<gFF2, 256>>>(pffn, W2, B2, px, DFFN, EE, px);
    }
    ln_kernel<1><<<NROWS, 128>>>(px, outp, gf, bf);
}

// round 8
// speedup vs baseline: 2.4314x; 1.3797x over previous
#include <cuda_runtime.h>
#include <cuda_bf16.h>
#include <stdint.h>

#define BB      2
#define SEQ     2048
#define EE      512
#define HH      8
#define DDIM    64
#define NLAYERS 2
#define DFFN    2048
#define NROWS   4096   // BB*SEQ

// flash attention tiles
#define BQ      128
#define BK      64
#define FA_SMEM_FLOATS (64*(BQ+4) + 64*(BK+4) + BK*68 + BQ*68 + BQ*17 + 3*BQ)
#define FA_SMEM_BYTES  (FA_SMEM_FLOATS*4 + BK*4)

// mma.sync GEMM config: 128x128 tile, K-chunk 32 (bf16), hi/lo x3 passes
#define GM_CHUNK     32
#define GM_STRIDE    80                    // smem bytes per row (64B data + 16B pad)
#define GM_MAT_BYTES (128 * GM_STRIDE)     // 10240
#define GM_BUF_BYTES (4 * GM_MAT_BYTES)    // Ahi, Alo, Bhi, Blo
#define GM_SMEM      (2 * GM_BUF_BYTES)    // double buffered: 81920

// ---------------- scratch (device globals) ----------------------------------
__device__ float g_x[NROWS * EE];
__device__ float g_q[NROWS * EE];
__device__ float g_k[NROWS * EE];
__device__ float g_v[NROWS * EE];
__device__ float g_attn[NROWS * EE];
__device__ __nv_bfloat16 g_hhi[NROWS * EE];
__device__ __nv_bfloat16 g_hlo[NROWS * EE];
__device__ __nv_bfloat16 g_fhi[NROWS * DFFN];
__device__ __nv_bfloat16 g_flo[NROWS * DFFN];
__device__ __nv_bfloat16 g_wqhi[NLAYERS*EE*EE], g_wqlo[NLAYERS*EE*EE];
__device__ __nv_bfloat16 g_wkhi[NLAYERS*EE*EE], g_wklo[NLAYERS*EE*EE];
__device__ __nv_bfloat16 g_wvhi[NLAYERS*EE*EE], g_wvlo[NLAYERS*EE*EE];
__device__ __nv_bfloat16 g_W1hi[DFFN*EE], g_W1lo[DFFN*EE];
__device__ __nv_bfloat16 g_W2hi[EE*DFFN], g_W2lo[EE*DFFN];

// ---------------- PTX helpers ------------------------------------------------
__device__ __forceinline__ uint32_t smem_u32(const void* p) {
    uint32_t a;
    asm("{ .reg .u64 t; cvta.to.shared.u64 t, %1; cvt.u32.u64 %0, t; }" : "=r"(a) : "l"(p));
    return a;
}
__device__ __forceinline__ void cp16(uint32_t saddr, const void* g) {
    asm volatile("cp.async.cg.shared.global [%0], [%1], 16;" :: "r"(saddr), "l"(g));
}
__device__ __forceinline__ void cp_commit() {
    asm volatile("cp.async.commit_group;" ::: "memory");
}
__device__ __forceinline__ void cp_wait0() {
    asm volatile("cp.async.wait_group 0;" ::: "memory");
}
__device__ __forceinline__ void ldmx4(uint32_t* r, uint32_t addr) {
    asm volatile("ldmatrix.sync.aligned.m8n8.x4.shared.b16 {%0,%1,%2,%3}, [%4];"
        : "=r"(r[0]), "=r"(r[1]), "=r"(r[2]), "=r"(r[3]) : "r"(addr));
}
__device__ __forceinline__ void mma_bf16(float* d, const uint32_t* a, const uint32_t* b) {
    asm volatile(
        "mma.sync.aligned.m16n8k16.row.col.f32.bf16.bf16.f32 "
        "{%0,%1,%2,%3}, {%4,%5,%6,%7}, {%8,%9}, {%0,%1,%2,%3};"
        : "+f"(d[0]), "+f"(d[1]), "+f"(d[2]), "+f"(d[3])
        : "r"(a[0]), "r"(a[1]), "r"(a[2]), "r"(a[3]), "r"(b[0]), "r"(b[1]));
}

// ---------------- hi/lo split ------------------------------------------------
__device__ __forceinline__ void split_bf16(float v, __nv_bfloat16& h, __nv_bfloat16& l) {
    h = __float2bfloat16(v);
    l = __float2bfloat16(v - __bfloat162float(h));
}

// ---------------- reductions -------------------------------------------------
__device__ __forceinline__ void block_reduce2(float& s, float& s2) {
    __shared__ float shm[8];
    #pragma unroll
    for (int o = 16; o > 0; o >>= 1) {
        s  += __shfl_down_sync(0xffffffffu, s,  o);
        s2 += __shfl_down_sync(0xffffffffu, s2, o);
    }
    int w = threadIdx.x >> 5;
    __syncthreads();
    if ((threadIdx.x & 31) == 0) { shm[w] = s; shm[4 + w] = s2; }
    __syncthreads();
    s  = shm[0] + shm[1] + shm[2] + shm[3];
    s2 = shm[4] + shm[5] + shm[6] + shm[7];
}

// ---------------- LayerNorm variants ----------------------------------------
__global__ void ln_f32(const float* __restrict__ in, float* __restrict__ outp,
                       const float* __restrict__ g, const float* __restrict__ b) {
    int row = blockIdx.x, t = threadIdx.x;
    const float* xr = in + (size_t)row * EE;
    float v[4], s = 0.f, s2 = 0.f;
    #pragma unroll
    for (int i = 0; i < 4; i++) { v[i] = xr[t + i*128]; s += v[i]; s2 += v[i]*v[i]; }
    block_reduce2(s, s2);
    float mu = s * (1.f/EE), var = s2 * (1.f/EE) - mu*mu, r = rsqrtf(var + 1e-5f);
    #pragma unroll
    for (int i = 0; i < 4; i++) {
        int idx = t + i*128;
        outp[(size_t)row*EE + idx] = (v[i]-mu)*r*g[idx] + b[idx];
    }
}
__global__ void ln_bf16(const float* __restrict__ in,
                        __nv_bfloat16* __restrict__ hi, __nv_bfloat16* __restrict__ lo,
                        const float* __restrict__ g, const float* __restrict__ b) {
    int row = blockIdx.x, t = threadIdx.x;
    const float* xr = in + (size_t)row * EE;
    float v[4], s = 0.f, s2 = 0.f;
    #pragma unroll
    for (int i = 0; i < 4; i++) { v[i] = xr[t + i*128]; s += v[i]; s2 += v[i]*v[i]; }
    block_reduce2(s, s2);
    float mu = s * (1.f/EE), var = s2 * (1.f/EE) - mu*mu, r = rsqrtf(var + 1e-5f);
    #pragma unroll
    for (int i = 0; i < 4; i++) {
        int idx = t + i*128;
        float y = (v[i]-mu)*r*g[idx] + b[idx];
        __nv_bfloat16 h, l; split_bf16(y, h, l);
        hi[(size_t)row*EE + idx] = h;
        lo[(size_t)row*EE + idx] = l;
    }
}
__global__ void fuse_attn_res_ln(const float* __restrict__ attn, float* x,
                                 __nv_bfloat16* __restrict__ hhi, __nv_bfloat16* __restrict__ hlo,
                                 const float* __restrict__ g2, const float* __restrict__ b2) {
    int row = blockIdx.x, t = threadIdx.x;
    const float* ar = attn + (size_t)row * EE;
    float a[4], s = 0.f, s2 = 0.f;
    #pragma unroll
    for (int i = 0; i < 4; i++) { a[i] = ar[t + i*128]; s += a[i]; s2 += a[i]*a[i]; }
    block_reduce2(s, s2);
    float mu = s * (1.f/EE), var = s2 * (1.f/EE) - mu*mu, r = rsqrtf(var + 1e-5f);
    float xv[4];
    s = 0.f; s2 = 0.f;
    #pragma unroll
    for (int i = 0; i < 4; i++) {
        int idx = t + i*128;
        float y = (a[i]-mu)*r*g2[idx] + b2[idx];
        float xn = x[(size_t)row*EE + idx] + y;
        x[(size_t)row*EE + idx] = xn;
        xv[i] = xn; s += xn; s2 += xn*xn;
    }
    block_reduce2(s, s2);
    float mu2 = s * (1.f/EE), var2 = s2 * (1.f/EE) - mu2*mu2, r2 = rsqrtf(var2 + 1e-5f);
    #pragma unroll
    for (int i = 0; i < 4; i++) {
        int idx = t + i*128;
        float y = (xv[i]-mu2)*r2;
        __nv_bfloat16 h, l; split_bf16(y, h, l);
        hhi[(size_t)row*EE + idx] = h;
        hlo[(size_t)row*EE + idx] = l;
    }
}

// ---------------- weight fp32 -> bf16 hi/lo ---------------------------------
__global__ void cvt_kernel(const float* __restrict__ in,
                           __nv_bfloat16* __restrict__ hi, __nv_bfloat16* __restrict__ lo, int n) {
    int i = blockIdx.x * blockDim.x + threadIdx.x;
    if (i < n) {
        __nv_bfloat16 h, l; split_bf16(in[i], h, l);
        hi[i] = h; lo[i] = l;
    }
}

// ---------------- mma.sync GEMM ----------------------------------------------
// C[128x128] tile: C = A.B^T, A[rows,K], B[cols,K], bf16 hi/lo, 3 passes.
// MODE 0: fp32+bias. MODE 1: bias+relu -> bf16 hi/lo. MODE 2: fp32+bias+residual.
template<int MODE>
__device__ __forceinline__ void gemm_mma_body(
    const __nv_bfloat16* __restrict__ Ahi, const __nv_bfloat16* __restrict__ Alo,
    const __nv_bfloat16* __restrict__ Bhi, const __nv_bfloat16* __restrict__ Blo,
    const float* __restrict__ bias, int K, int N,
    float* __restrict__ Cf, __nv_bfloat16* __restrict__ Chi, __nv_bfloat16* __restrict__ Clo,
    const float* __restrict__ res, int rowBase, int colBase)
{
    extern __shared__ char sm8[];
    uint32_t sbase = smem_u32(sm8);
    int tid = threadIdx.x, lane = tid & 31, warp = tid >> 5;
    int wm = warp >> 2, wn = warp & 3;          // 2 x 4 warp grid

    float acc[4][4][4];
    #pragma unroll
    for (int i = 0; i < 4; i++)
        #pragma unroll
        for (int j = 0; j < 4; j++)
            #pragma unroll
            for (int c = 0; c < 4; c++) acc[i][j][c] = 0.f;

    // ldmatrix per-lane address components (bytes)
    uint32_t aAddr = (uint32_t)((wm*64 + ((lane>>3)&1)*8 + (lane&7)) * GM_STRIDE
                                + (lane>>4)*16);
    uint32_t bAddr = (uint32_t)((wn*32 + (lane>>4)*8 + (lane&7)) * GM_STRIDE
                                + ((lane>>3)&1)*16);

    const int T = K / GM_CHUNK;
    int lrow0 = tid >> 2, lseg = tid & 3;

    // prefetch chunk 0 into buffer 0
    {
        uint32_t sb = sbase;
        #pragma unroll
        for (int j = 0; j < 2; j++) {
            int row = lrow0 + j*64;
            uint32_t so = row*GM_STRIDE + lseg*16;
            size_t ga = (size_t)(rowBase+row)*K + lseg*8;
            size_t gb = (size_t)(colBase+row)*K + lseg*8;
            cp16(sb + 0*GM_MAT_BYTES + so, Ahi + ga);
            cp16(sb + 1*GM_MAT_BYTES + so, Alo + ga);
            cp16(sb + 2*GM_MAT_BYTES + so, Bhi + gb);
            cp16(sb + 3*GM_MAT_BYTES + so, Blo + gb);
        }
        cp_commit();
    }

    for (int t = 0; t < T; t++) {
        cp_wait0();
        __syncthreads();
        if (t + 1 < T) {
            uint32_t sb = sbase + ((t+1) & 1) * GM_BUF_BYTES;
            int koff = (t+1) * GM_CHUNK;
            #pragma unroll
            for (int j = 0; j < 2; j++) {
                int row = lrow0 + j*64;
                uint32_t so = row*GM_STRIDE + lseg*16;
                size_t ga = (size_t)(rowBase+row)*K + koff + lseg*8;
                size_t gb = (size_t)(colBase+row)*K + koff + lseg*8;
                cp16(sb + 0*GM_MAT_BYTES + so, Ahi + ga);
                cp16(sb + 1*GM_MAT_BYTES + so, Alo + ga);
                cp16(sb + 2*GM_MAT_BYTES + so, Bhi + gb);
                cp16(sb + 3*GM_MAT_BYTES + so, Blo + gb);
            }
            cp_commit();
        }
        uint32_t buf = sbase + (t & 1) * GM_BUF_BYTES;
        #pragma unroll
        for (int ks = 0; ks < 2; ks++) {
            uint32_t ah[4][4], al[4][4], bh[2][4], bl[2][4];
            #pragma unroll
            for (int i = 0; i < 4; i++) {
                uint32_t ad = buf + aAddr + i*16*GM_STRIDE + ks*32;
                ldmx4(ah[i], ad);
                ldmx4(al[i], ad + GM_MAT_BYTES);
            }
            #pragma unroll
            for (int p = 0; p < 2; p++) {
                uint32_t bd = buf + 2*GM_MAT_BYTES + bAddr + p*16*GM_STRIDE + ks*32;
                ldmx4(bh[p], bd);
                ldmx4(bl[p], bd + GM_MAT_BYTES);
            }
            #pragma unroll
            for (int i = 0; i < 4; i++)
                #pragma unroll
                for (int j = 0; j < 4; j++) {
                    const uint32_t* bhp = &bh[j>>1][(j&1)*2];
                    const uint32_t* blp = &bl[j>>1][(j&1)*2];
                    mma_bf16(acc[i][j], ah[i], bhp);
                    mma_bf16(acc[i][j], ah[i], blp);
                    mma_bf16(acc[i][j], al[i], bhp);
                }
        }
    }

    // epilogue: c-frag layout: rows g, g+8; cols tg*2, tg*2+1
    int g = lane >> 2, tg = lane & 3;
    #pragma unroll
    for (int i = 0; i < 4; i++) {
        int r0 = rowBase + wm*64 + i*16 + g;
        #pragma unroll
        for (int j = 0; j < 4; j++) {
            int c = colBase + wn*32 + j*8 + tg*2;
            float b0 = bias[c], b1 = bias[c+1];
            #pragma unroll
            for (int half = 0; half < 2; half++) {
                int r = r0 + half*8;
                float v0 = acc[i][j][half*2+0] + b0;
                float v1 = acc[i][j][half*2+1] + b1;
                if (MODE == 1) {
                    v0 = fmaxf(v0, 0.f); v1 = fmaxf(v1, 0.f);
                    __nv_bfloat16 h0, l0, h1, l1;
                    split_bf16(v0, h0, l0); split_bf16(v1, h1, l1);
                    __nv_bfloat162 hp; hp.x = h0; hp.y = h1;
                    __nv_bfloat162 lp; lp.x = l0; lp.y = l1;
                    *(__nv_bfloat162*)&Chi[(size_t)r * N + c] = hp;
                    *(__nv_bfloat162*)&Clo[(size_t)r * N + c] = lp;
                } else {
                    if (MODE == 2) {
                        float2 rv = *(const float2*)&res[(size_t)r * N + c];
                        v0 += rv.x; v1 += rv.y;
                    }
                    float2 o; o.x = v0; o.y = v1;
                    *(float2*)&Cf[(size_t)r * N + c] = o;
                }
            }
        }
    }
}

template<int MODE>
__global__ __launch_bounds__(256) void gemm_mma(
    const __nv_bfloat16* __restrict__ Ahi, const __nv_bfloat16* __restrict__ Alo,
    const __nv_bfloat16* __restrict__ Bhi, const __nv_bfloat16* __restrict__ Blo,
    const float* __restrict__ bias, int K, int N,
    float* __restrict__ Cf, __nv_bfloat16* __restrict__ Chi, __nv_bfloat16* __restrict__ Clo,
    const float* __restrict__ res)
{
    gemm_mma_body<MODE>(Ahi, Alo, Bhi, Blo, bias, K, N, Cf, Chi, Clo, res,
                        blockIdx.y * 128, blockIdx.x * 128);
}

__global__ __launch_bounds__(256) void gemm_mma_qkv(
    const __nv_bfloat16* __restrict__ hhi, const __nv_bfloat16* __restrict__ hlo,
    const __nv_bfloat16* __restrict__ wqh, const __nv_bfloat16* __restrict__ wql,
    const __nv_bfloat16* __restrict__ wkh, const __nv_bfloat16* __restrict__ wkl,
    const __nv_bfloat16* __restrict__ wvh, const __nv_bfloat16* __restrict__ wvl,
    const float* __restrict__ bq, const float* __restrict__ bk, const float* __restrict__ bv,
    float* __restrict__ q, float* __restrict__ k, float* __restrict__ v)
{
    const __nv_bfloat16 *Bh, *Bl; const float* bi; float* C;
    if (blockIdx.z == 0)      { Bh = wqh; Bl = wql; bi = bq; C = q; }
    else if (blockIdx.z == 1) { Bh = wkh; Bl = wkl; bi = bk; C = k; }
    else                      { Bh = wvh; Bl = wvl; bi = bv; C = v; }
    gemm_mma_body<0>(hhi, hlo, Bh, Bl, bi, EE, EE, C, nullptr, nullptr, nullptr,
                     blockIdx.y * 128, blockIdx.x * 128);
}

// ---------------- Flash attention (unchanged from R6) ------------------------
__global__ __launch_bounds__(256, 1) void flash_attn_kernel(
    const float* __restrict__ q, const float* __restrict__ k,
    const float* __restrict__ v, const int* __restrict__ mask,
    float* __restrict__ out)
{
    extern __shared__ float sm[];
    float* sQt   = sm;
    float* sKt   = sQt + 64 * (BQ + 4);
    float* sV    = sKt + 64 * (BK + 4);
    float* sP    = sV + BK * 68;
    float* sRed  = sP + BQ * 68;
    float* sM    = sRed + BQ * 17;
    float* sL    = sM + BQ;
    float* sScl  = sL + BQ;
    int*   sMask = (int*)(sScl + BQ);

    int tid = threadIdx.x;
    int tx = tid & 15;
    int ty = tid >> 4;
    int q0 = blockIdx.x * BQ;
    int h  = blockIdx.y;
    int b  = blockIdx.z;
    const float* qb = q + ((size_t)b * SEQ) * EE + h * DDIM;
    const float* kb = k + ((size_t)b * SEQ) * EE + h * DDIM;
    const float* vb = v + ((size_t)b * SEQ) * EE + h * DDIM;
    const int*   mb = mask + (size_t)b * SEQ;

    int rows[8];
    #pragma unroll
    for (int i = 0; i < 8; i++) rows[i] = (i < 4) ? (ty * 4 + i) : (64 + ty * 4 + i - 4);

    #pragma unroll
    for (int i = 0; i < 8; i++) {
        int g  = tid + i * 256;
        int r  = g >> 4;
        int d4 = (g & 15) << 2;
        float4 qv = *(const float4*)&qb[(size_t)(q0 + r) * EE + d4];
        sQt[(d4 + 0) * (BQ + 4) + r] = qv.x;
        sQt[(d4 + 1) * (BQ + 4) + r] = qv.y;
        sQt[(d4 + 2) * (BQ + 4) + r] = qv.z;
        sQt[(d4 + 3) * (BQ + 4) + r] = qv.w;
    }
    if (tid < BQ) { sM[tid] = -1e30f; sL[tid] = 0.f; }
    float accO[8][4];
    #pragma unroll
    for (int i = 0; i < 8; i++)
        #pragma unroll
        for (int j = 0; j < 4; j++) accO[i][j] = 0.f;
    __syncthreads();

    for (int kt = 0; kt < SEQ; kt += BK) {
        #pragma unroll
        for (int i = 0; i < 4; i++) {
            int g  = tid + i * 256;
            int r  = g >> 4;
            int d4 = (g & 15) << 2;
            float4 kv = *(const float4*)&kb[(size_t)(kt + r) * EE + d4];
            sKt[(d4 + 0) * (BK + 4) + r] = kv.x;
            sKt[(d4 + 1) * (BK + 4) + r] = kv.y;
            sKt[(d4 + 2) * (BK + 4) + r] = kv.z;
            sKt[(d4 + 3) * (BK + 4) + r] = kv.w;
            float4 vv = *(const float4*)&vb[(size_t)(kt + r) * EE + d4];
            *(float4*)&sV[r * 68 + d4] = vv;
        }
        if (tid < BK) sMask[tid] = mb[kt + tid];
        __syncthreads();

        float accS[8][4];
        #pragma unroll
        for (int i = 0; i < 8; i++)
            #pragma unroll
            for (int j = 0; j < 4; j++) accS[i][j] = 0.f;
        #pragma unroll 8
        for (int d = 0; d < DDIM; d++) {
            float4 a0 = *(const float4*)&sQt[d * (BQ + 4) + ty * 4];
            float4 a1 = *(const float4*)&sQt[d * (BQ + 4) + 64 + ty * 4];
            float4 bv4 = *(const float4*)&sKt[d * (BK + 4) + tx * 4];
            float aa[8] = {a0.x, a0.y, a0.z, a0.w, a1.x, a1.y, a1.z, a1.w};
            #pragma unroll
            for (int i = 0; i < 8; i++) {
                accS[i][0] += aa[i] * bv4.x;
                accS[i][1] += aa[i] * bv4.y;
                accS[i][2] += aa[i] * bv4.z;
                accS[i][3] += aa[i] * bv4.w;
            }
        }
        int mk[4];
        #pragma unroll
        for (int j = 0; j < 4; j++) mk[j] = sMask[tx * 4 + j];
        #pragma unroll
        for (int i = 0; i < 8; i++) {
            float m = -1e30f;
            #pragma unroll
            for (int j = 0; j < 4; j++) {
                accS[i][j] = mk[j] ? -1e30f : accS[i][j] * 0.125f;
                m = fmaxf(m, accS[i][j]);
            }
            sRed[rows[i] * 17 + tx] = m;
        }
        __syncthreads();
        if (tid < BQ) {
            float m = sRed[tid * 17];
            #pragma unroll
            for (int t2 = 1; t2 < 16; t2++) m = fmaxf(m, sRed[tid * 17 + t2]);
            float mo = sM[tid];
            float mn = fmaxf(mo, m);
            sM[tid]   = mn;
            sScl[tid] = __expf(mo - mn);
        }
        __syncthreads();
        #pragma unroll
        for (int i = 0; i < 8; i++) {
            int row = rows[i];
            float mn  = sM[row];
            float scl = sScl[row];
            float4 p;
            p.x = mk[0] ? 0.f : __expf(accS[i][0] - mn);
            p.y = mk[1] ? 0.f : __expf(accS[i][1] - mn);
            p.z = mk[2] ? 0.f : __expf(accS[i][2] - mn);
            p.w = mk[3] ? 0.f : __expf(accS[i][3] - mn);
            *(float4*)&sP[row * 68 + tx * 4] = p;
            sRed[row * 17 + tx] = p.x + p.y + p.z + p.w;
            #pragma unroll
            for (int j = 0; j < 4; j++) accO[i][j] *= scl;
        }
        __syncthreads();
        if (tid < BQ) {
            float l = 0.f;
            #pragma unroll
            for (int t2 = 0; t2 < 16; t2++) l += sRed[tid * 17 + t2];
            sL[tid] = sL[tid] * sScl[tid] + l;
        }
        #pragma unroll 4
        for (int kk = 0; kk < BK; kk += 4) {
            float4 b0 = *(const float4*)&sV[(kk + 0) * 68 + tx * 4];
            float4 b1 = *(const float4*)&sV[(kk + 1) * 68 + tx * 4];
            float4 b2 = *(const float4*)&sV[(kk + 2) * 68 + tx * 4];
            float4 b3 = *(const float4*)&sV[(kk + 3) * 68 + tx * 4];
            #pragma unroll
            for (int i = 0; i < 8; i++) {
                float4 a = *(const float4*)&sP[rows[i] * 68 + kk];
                accO[i][0] += a.x * b0.x + a.y * b1.x + a.z * b2.x + a.w * b3.x;
                accO[i][1] += a.x * b0.y + a.y * b1.y + a.z * b2.y + a.w * b3.y;
                accO[i][2] += a.x * b0.z + a.y * b1.z + a.z * b2.z + a.w * b3.z;
                accO[i][3] += a.x * b0.w + a.y * b1.w + a.z * b2.w + a.w * b3.w;
            }
        }
        __syncthreads();
    }
    #pragma unroll
    for (int i = 0; i < 8; i++) {
        int row = rows[i];
        float inv = 1.f / sL[row];
        float4 o;
        o.x = accO[i][0] * inv; o.y = accO[i][1] * inv;
        o.z = accO[i][2] * inv; o.w = accO[i][3] * inv;
        *(float4*)&out[(size_t)(b * SEQ + q0 + row) * EE + h * DDIM + tx * 4] = o;
    }
}

// ---------------- misc ------------------------------------------------------
__global__ void copy_f4(const float4* __restrict__ in, float4* __restrict__ out, int n4) {
    int i = blockIdx.x * blockDim.x + threadIdx.x;
    if (i < n4) out[i] = in[i];
}

// ---------------- launch ----------------------------------------------------
extern "C" void kernel_launch(void* const* d_in, const int* in_sizes, int n_in,
                              void* d_out, int out_size) {
    const float* x_in = (const float*)d_in[0];
    const int* mask = (const int*)d_in[1];
    const float* wq = (const float*)d_in[2];
    const float* bq = (const float*)d_in[3];
    const float* wk = (const float*)d_in[4];
    const float* bk = (const float*)d_in[5];
    const float* wv = (const float*)d_in[6];
    const float* bv = (const float*)d_in[7];
    const float* g1 = (const float*)d_in[8];
    const float* b1 = (const float*)d_in[9];
    const float* g2 = (const float*)d_in[10];
    const float* b2 = (const float*)d_in[11];
    const float* gf = (const float*)d_in[12];
    const float* bf = (const float*)d_in[13];
    const float* W1 = (const float*)d_in[14];
    const float* B1 = (const float*)d_in[15];
    const float* W2 = (const float*)d_in[16];
    const float* B2 = (const float*)d_in[17];
    float* outp = (float*)d_out;

    float *px, *pq, *pk, *pv, *pattn;
    __nv_bfloat16 *phhi, *phlo, *pfhi, *pflo;
    __nv_bfloat16 *pwqh, *pwql, *pwkh, *pwkl, *pwvh, *pwvl, *pW1h, *pW1l, *pW2h, *pW2l;
    cudaGetSymbolAddress((void**)&px,    g_x);
    cudaGetSymbolAddress((void**)&pq,    g_q);
    cudaGetSymbolAddress((void**)&pk,    g_k);
    cudaGetSymbolAddress((void**)&pv,    g_v);
    cudaGetSymbolAddress((void**)&pattn, g_attn);
    cudaGetSymbolAddress((void**)&phhi,  g_hhi);
    cudaGetSymbolAddress((void**)&phlo,  g_hlo);
    cudaGetSymbolAddress((void**)&pfhi,  g_fhi);
    cudaGetSymbolAddress((void**)&pflo,  g_flo);
    cudaGetSymbolAddress((void**)&pwqh,  g_wqhi);
    cudaGetSymbolAddress((void**)&pwql,  g_wqlo);
    cudaGetSymbolAddress((void**)&pwkh,  g_wkhi);
    cudaGetSymbolAddress((void**)&pwkl,  g_wklo);
    cudaGetSymbolAddress((void**)&pwvh,  g_wvhi);
    cudaGetSymbolAddress((void**)&pwvl,  g_wvlo);
    cudaGetSymbolAddress((void**)&pW1h,  g_W1hi);
    cudaGetSymbolAddress((void**)&pW1l,  g_W1lo);
    cudaGetSymbolAddress((void**)&pW2h,  g_W2hi);
    cudaGetSymbolAddress((void**)&pW2l,  g_W2lo);

    cudaFuncSetAttribute(flash_attn_kernel,
                         cudaFuncAttributeMaxDynamicSharedMemorySize, FA_SMEM_BYTES);
    cudaFuncSetAttribute(gemm_mma_qkv,
                         cudaFuncAttributeMaxDynamicSharedMemorySize, GM_SMEM);
    cudaFuncSetAttribute(gemm_mma<1>,
                         cudaFuncAttributeMaxDynamicSharedMemorySize, GM_SMEM);
    cudaFuncSetAttribute(gemm_mma<2>,
                         cudaFuncAttributeMaxDynamicSharedMemorySize, GM_SMEM);

    {
        int n4 = NROWS * EE / 4;
        copy_f4<<<(n4 + 255) / 256, 256>>>((const float4*)x_in, (float4*)px, n4);
    }
    {
        int nq = NLAYERS * EE * EE;
        cvt_kernel<<<(nq + 255) / 256, 256>>>(wq, pwqh, pwql, nq);
        cvt_kernel<<<(nq + 255) / 256, 256>>>(wk, pwkh, pwkl, nq);
        cvt_kernel<<<(nq + 255) / 256, 256>>>(wv, pwvh, pwvl, nq);
        int n1 = DFFN * EE;
        cvt_kernel<<<(n1 + 255) / 256, 256>>>(W1, pW1h, pW1l, n1);
        int n2 = EE * DFFN;
        cvt_kernel<<<(n2 + 255) / 256, 256>>>(W2, pW2h, pW2l, n2);
    }

    dim3 gQKV(EE / 128, NROWS / 128, 3);   // (4, 32, 3)
    dim3 gFF1(DFFN / 128, NROWS / 128);    // (16, 32)
    dim3 gFF2(EE / 128, NROWS / 128);      // (4, 32)
    dim3 gAtt(SEQ / BQ, HH, BB);           // (16, 8, 2)

    for (int l = 0; l < NLAYERS; l++) {
        const __nv_bfloat16* wqh = pwqh + (size_t)l * EE * EE;
        const __nv_bfloat16* wql = pwql + (size_t)l * EE * EE;
        const __nv_bfloat16* wkh = pwkh + (size_t)l * EE * EE;
        const __nv_bfloat16* wkl = pwkl + (size_t)l * EE * EE;
        const __nv_bfloat16* wvh = pwvh + (size_t)l * EE * EE;
        const __nv_bfloat16* wvl = pwvl + (size_t)l * EE * EE;
        const float* bql = bq + (size_t)l * EE;
        const float* bkl = bk + (size_t)l * EE;
        const float* bvl = bv + (size_t)l * EE;

        ln_bf16<<<NROWS, 128>>>(px, phhi, phlo, g1, b1);
        gemm_mma_qkv<<<gQKV, 256, GM_SMEM>>>(phhi, phlo,
            wqh, wql, wkh, wkl, wvh, wvl, bql, bkl, bvl, pq, pk, pv);
        flash_attn_kernel<<<gAtt, 256, FA_SMEM_BYTES>>>(pq, pk, pv, mask, pattn);
        fuse_attn_res_ln<<<NROWS, 128>>>(pattn, px, phhi, phlo, g2, b2);
        gemm_mma<1><<<gFF1, 256, GM_SMEM>>>(phhi, phlo, pW1h, pW1l,
            B1, EE, DFFN, nullptr, pfhi, pflo, nullptr);
        gemm_mma<2><<<gFF2, 256, GM_SMEM>>>(pfhi, pflo, pW2h, pW2l,
            B2, DFFN, EE, px, nullptr, nullptr, px);
    }
    ln_f32<<<NROWS, 128>>>(px, outp, gf, bf);
}

// round 9
// speedup vs baseline: 3.9225x; 1.6133x over previous
#include <cuda_runtime.h>
#include <cuda_bf16.h>
#include <stdint.h>
#include <string.h>

#define BB      2
#define SEQ     2048
#define EE      512
#define HH      8
#define DDIM    64
#define NLAYERS 2
#define DFFN    2048
#define NROWS   4096   // BB*SEQ

// mma.sync GEMM config: 128x128 tile, K-chunk 32 (bf16), hi/lo x3 passes
#define GM_CHUNK     32
#define GM_STRIDE    80
#define GM_MAT_BYTES (128 * GM_STRIDE)
#define GM_BUF_BYTES (4 * GM_MAT_BYTES)
#define GM_SMEM      (2 * GM_BUF_BYTES)

// flash mma config: BQ=128, BK=32, 8 warps (16 q-rows each)
#define FB_STRIDE_B  144                   // 64 bf16 = 128B + 16B pad
#define FB_Q_BYTES   (128 * FB_STRIDE_B)   // 18432 per matrix (hi or lo)
#define FB_KV_MAT    (32 * FB_STRIDE_B)    // 4608
#define FB_STAGE     (4 * FB_KV_MAT)       // Kh,Kl,Vh,Vl = 18432
#define FB_SMEM      (2*FB_Q_BYTES + 2*FB_STAGE + 256)

// ---------------- scratch (device globals) ----------------------------------
__device__ float g_x[NROWS * EE];
__device__ float g_attn[NROWS * EE];
__device__ __nv_bfloat16 g_qhi[NROWS*EE], g_qlo[NROWS*EE];
__device__ __nv_bfloat16 g_khi[NROWS*EE], g_klo[NROWS*EE];
__device__ __nv_bfloat16 g_vhi[NROWS*EE], g_vlo[NROWS*EE];
__device__ __nv_bfloat16 g_hhi[NROWS * EE];
__device__ __nv_bfloat16 g_hlo[NROWS * EE];
__device__ __nv_bfloat16 g_fhi[NROWS * DFFN];
__device__ __nv_bfloat16 g_flo[NROWS * DFFN];
__device__ __nv_bfloat16 g_wqhi[NLAYERS*EE*EE], g_wqlo[NLAYERS*EE*EE];
__device__ __nv_bfloat16 g_wkhi[NLAYERS*EE*EE], g_wklo[NLAYERS*EE*EE];
__device__ __nv_bfloat16 g_wvhi[NLAYERS*EE*EE], g_wvlo[NLAYERS*EE*EE];
__device__ __nv_bfloat16 g_W1hi[DFFN*EE], g_W1lo[DFFN*EE];
__device__ __nv_bfloat16 g_W2hi[EE*DFFN], g_W2lo[EE*DFFN];

// ---------------- PTX helpers ------------------------------------------------
__device__ __forceinline__ uint32_t smem_u32(const void* p) {
    uint32_t a;
    asm("{ .reg .u64 t; cvta.to.shared.u64 t, %1; cvt.u32.u64 %0, t; }" : "=r"(a) : "l"(p));
    return a;
}
__device__ __forceinline__ void cp16(uint32_t saddr, const void* g) {
    asm volatile("cp.async.cg.shared.global [%0], [%1], 16;" :: "r"(saddr), "l"(g));
}
__device__ __forceinline__ void cp_commit() {
    asm volatile("cp.async.commit_group;" ::: "memory");
}
__device__ __forceinline__ void cp_wait0() {
    asm volatile("cp.async.wait_group 0;" ::: "memory");
}
__device__ __forceinline__ void cp_wait1() {
    asm volatile("cp.async.wait_group 1;" ::: "memory");
}
__device__ __forceinline__ void ldmx4(uint32_t* r, uint32_t addr) {
    asm volatile("ldmatrix.sync.aligned.m8n8.x4.shared.b16 {%0,%1,%2,%3}, [%4];"
        : "=r"(r[0]), "=r"(r[1]), "=r"(r[2]), "=r"(r[3]) : "r"(addr));
}
__device__ __forceinline__ void ldmx4t(uint32_t* r, uint32_t addr) {
    asm volatile("ldmatrix.sync.aligned.m8n8.x4.trans.shared.b16 {%0,%1,%2,%3}, [%4];"
        : "=r"(r[0]), "=r"(r[1]), "=r"(r[2]), "=r"(r[3]) : "r"(addr));
}
__device__ __forceinline__ void mma_bf16(float* d, const uint32_t* a, const uint32_t* b) {
    asm volatile(
        "mma.sync.aligned.m16n8k16.row.col.f32.bf16.bf16.f32 "
        "{%0,%1,%2,%3}, {%4,%5,%6,%7}, {%8,%9}, {%0,%1,%2,%3};"
        : "+f"(d[0]), "+f"(d[1]), "+f"(d[2]), "+f"(d[3])
        : "r"(a[0]), "r"(a[1]), "r"(a[2]), "r"(a[3]), "r"(b[0]), "r"(b[1]));
}

// ---------------- hi/lo split ------------------------------------------------
__device__ __forceinline__ void split_bf16(float v, __nv_bfloat16& h, __nv_bfloat16& l) {
    h = __float2bfloat16(v);
    l = __float2bfloat16(v - __bfloat162float(h));
}
__device__ __forceinline__ void pack_hilo(float a, float b, uint32_t& h, uint32_t& l) {
    __nv_bfloat162 hp, lp;
    hp.x = __float2bfloat16(a);
    hp.y = __float2bfloat16(b);
    lp.x = __float2bfloat16(a - __bfloat162float(hp.x));
    lp.y = __float2bfloat16(b - __bfloat162float(hp.y));
    h = *reinterpret_cast<uint32_t*>(&hp);
    l = *reinterpret_cast<uint32_t*>(&lp);
}

// ---------------- reductions -------------------------------------------------
__device__ __forceinline__ void block_reduce2(float& s, float& s2) {
    __shared__ float shm[8];
    #pragma unroll
    for (int o = 16; o > 0; o >>= 1) {
        s  += __shfl_down_sync(0xffffffffu, s,  o);
        s2 += __shfl_down_sync(0xffffffffu, s2, o);
    }
    int w = threadIdx.x >> 5;
    __syncthreads();
    if ((threadIdx.x & 31) == 0) { shm[w] = s; shm[4 + w] = s2; }
    __syncthreads();
    s  = shm[0] + shm[1] + shm[2] + shm[3];
    s2 = shm[4] + shm[5] + shm[6] + shm[7];
}

// ---------------- LayerNorm variants ----------------------------------------
__global__ void ln_f32(const float* __restrict__ in, float* __restrict__ outp,
                       const float* __restrict__ g, const float* __restrict__ b) {
    int row = blockIdx.x, t = threadIdx.x;
    const float* xr = in + (size_t)row * EE;
    float v[4], s = 0.f, s2 = 0.f;
    #pragma unroll
    for (int i = 0; i < 4; i++) { v[i] = xr[t + i*128]; s += v[i]; s2 += v[i]*v[i]; }
    block_reduce2(s, s2);
    float mu = s * (1.f/EE), var = s2 * (1.f/EE) - mu*mu, r = rsqrtf(var + 1e-5f);
    #pragma unroll
    for (int i = 0; i < 4; i++) {
        int idx = t + i*128;
        outp[(size_t)row*EE + idx] = (v[i]-mu)*r*g[idx] + b[idx];
    }
}
__global__ void ln_bf16(const float* __restrict__ in,
                        __nv_bfloat16* __restrict__ hi, __nv_bfloat16* __restrict__ lo,
                        const float* __restrict__ g, const float* __restrict__ b) {
    int row = blockIdx.x, t = threadIdx.x;
    const float* xr = in + (size_t)row * EE;
    float v[4], s = 0.f, s2 = 0.f;
    #pragma unroll
    for (int i = 0; i < 4; i++) { v[i] = xr[t + i*128]; s += v[i]; s2 += v[i]*v[i]; }
    block_reduce2(s, s2);
    float mu = s * (1.f/EE), var = s2 * (1.f/EE) - mu*mu, r = rsqrtf(var + 1e-5f);
    #pragma unroll
    for (int i = 0; i < 4; i++) {
        int idx = t + i*128;
        float y = (v[i]-mu)*r*g[idx] + b[idx];
        __nv_bfloat16 h, l; split_bf16(y, h, l);
        hi[(size_t)row*EE + idx] = h;
        lo[(size_t)row*EE + idx] = l;
    }
}
__global__ void fuse_attn_res_ln(const float* __restrict__ attn, float* x,
                                 __nv_bfloat16* __restrict__ hhi, __nv_bfloat16* __restrict__ hlo,
                                 const float* __restrict__ g2, const float* __restrict__ b2) {
    int row = blockIdx.x, t = threadIdx.x;
    const float* ar = attn + (size_t)row * EE;
    float a[4], s = 0.f, s2 = 0.f;
    #pragma unroll
    for (int i = 0; i < 4; i++) { a[i] = ar[t + i*128]; s += a[i]; s2 += a[i]*a[i]; }
    block_reduce2(s, s2);
    float mu = s * (1.f/EE), var = s2 * (1.f/EE) - mu*mu, r = rsqrtf(var + 1e-5f);
    float xv[4];
    s = 0.f; s2 = 0.f;
    #pragma unroll
    for (int i = 0; i < 4; i++) {
        int idx = t + i*128;
        float y = (a[i]-mu)*r*g2[idx] + b2[idx];
        float xn = x[(size_t)row*EE + idx] + y;
        x[(size_t)row*EE + idx] = xn;
        xv[i] = xn; s += xn; s2 += xn*xn;
    }
    block_reduce2(s, s2);
    float mu2 = s * (1.f/EE), var2 = s2 * (1.f/EE) - mu2*mu2, r2 = rsqrtf(var2 + 1e-5f);
    #pragma unroll
    for (int i = 0; i < 4; i++) {
        int idx = t + i*128;
        float y = (xv[i]-mu2)*r2;
        __nv_bfloat16 h, l; split_bf16(y, h, l);
        hhi[(size_t)row*EE + idx] = h;
        hlo[(size_t)row*EE + idx] = l;
    }
}

// ---------------- weight fp32 -> bf16 hi/lo ---------------------------------
__global__ void cvt_kernel(const float* __restrict__ in,
                           __nv_bfloat16* __restrict__ hi, __nv_bfloat16* __restrict__ lo, int n) {
    int i = blockIdx.x * blockDim.x + threadIdx.x;
    if (i < n) {
        __nv_bfloat16 h, l; split_bf16(in[i], h, l);
        hi[i] = h; lo[i] = l;
    }
}

// ---------------- mma.sync GEMM ----------------------------------------------
// MODE 1: bias+relu -> bf16 hi/lo. MODE 2: fp32+bias+residual. MODE 3: bias -> bf16 hi/lo.
template<int MODE>
__device__ __forceinline__ void gemm_mma_body(
    const __nv_bfloat16* __restrict__ Ahi, const __nv_bfloat16* __restrict__ Alo,
    const __nv_bfloat16* __restrict__ Bhi, const __nv_bfloat16* __restrict__ Blo,
    const float* __restrict__ bias, int K, int N,
    float* __restrict__ Cf, __nv_bfloat16* __restrict__ Chi, __nv_bfloat16* __restrict__ Clo,
    const float* __restrict__ res, int rowBase, int colBase)
{
    extern __shared__ char sm8[];
    uint32_t sbase = smem_u32(sm8);
    int tid = threadIdx.x, lane = tid & 31, warp = tid >> 5;
    int wm = warp >> 2, wn = warp & 3;

    float acc[4][4][4];
    #pragma unroll
    for (int i = 0; i < 4; i++)
        #pragma unroll
        for (int j = 0; j < 4; j++)
            #pragma unroll
            for (int c = 0; c < 4; c++) acc[i][j][c] = 0.f;

    uint32_t aAddr = (uint32_t)((wm*64 + ((lane>>3)&1)*8 + (lane&7)) * GM_STRIDE
                                + (lane>>4)*16);
    uint32_t bAddr = (uint32_t)((wn*32 + (lane>>4)*8 + (lane&7)) * GM_STRIDE
                                + ((lane>>3)&1)*16);

    const int T = K / GM_CHUNK;
    int lrow0 = tid >> 2, lseg = tid & 3;

    {
        uint32_t sb = sbase;
        #pragma unroll
        for (int j = 0; j < 2; j++) {
            int row = lrow0 + j*64;
            uint32_t so = row*GM_STRIDE + lseg*16;
            size_t ga = (size_t)(rowBase+row)*K + lseg*8;
            size_t gb = (size_t)(colBase+row)*K + lseg*8;
            cp16(sb + 0*GM_MAT_BYTES + so, Ahi + ga);
            cp16(sb + 1*GM_MAT_BYTES + so, Alo + ga);
            cp16(sb + 2*GM_MAT_BYTES + so, Bhi + gb);
            cp16(sb + 3*GM_MAT_BYTES + so, Blo + gb);
        }
        cp_commit();
    }

    for (int t = 0; t < T; t++) {
        cp_wait0();
        __syncthreads();
        if (t + 1 < T) {
            uint32_t sb = sbase + ((t+1) & 1) * GM_BUF_BYTES;
            int koff = (t+1) * GM_CHUNK;
            #pragma unroll
            for (int j = 0; j < 2; j++) {
                int row = lrow0 + j*64;
                uint32_t so = row*GM_STRIDE + lseg*16;
                size_t ga = (size_t)(rowBase+row)*K + koff + lseg*8;
                size_t gb = (size_t)(colBase+row)*K + koff + lseg*8;
                cp16(sb + 0*GM_MAT_BYTES + so, Ahi + ga);
                cp16(sb + 1*GM_MAT_BYTES + so, Alo + ga);
                cp16(sb + 2*GM_MAT_BYTES + so, Bhi + gb);
                cp16(sb + 3*GM_MAT_BYTES + so, Blo + gb);
            }
            cp_commit();
        }
        uint32_t buf = sbase + (t & 1) * GM_BUF_BYTES;
        #pragma unroll
        for (int ks = 0; ks < 2; ks++) {
            uint32_t ah[4][4], al[4][4], bh[2][4], bl[2][4];
            #pragma unroll
            for (int i = 0; i < 4; i++) {
                uint32_t ad = buf + aAddr + i*16*GM_STRIDE + ks*32;
                ldmx4(ah[i], ad);
                ldmx4(al[i], ad + GM_MAT_BYTES);
            }
            #pragma unroll
            for (int p = 0; p < 2; p++) {
                uint32_t bd = buf + 2*GM_MAT_BYTES + bAddr + p*16*GM_STRIDE + ks*32;
                ldmx4(bh[p], bd);
                ldmx4(bl[p], bd + GM_MAT_BYTES);
            }
            #pragma unroll
            for (int i = 0; i < 4; i++)
                #pragma unroll
                for (int j = 0; j < 4; j++) {
                    const uint32_t* bhp = &bh[j>>1][(j&1)*2];
                    const uint32_t* blp = &bl[j>>1][(j&1)*2];
                    mma_bf16(acc[i][j], ah[i], bhp);
                    mma_bf16(acc[i][j], ah[i], blp);
                    mma_bf16(acc[i][j], al[i], bhp);
                }
        }
    }

    int g = lane >> 2, tg = lane & 3;
    #pragma unroll
    for (int i = 0; i < 4; i++) {
        int r0 = rowBase + wm*64 + i*16 + g;
        #pragma unroll
        for (int j = 0; j < 4; j++) {
            int c = colBase + wn*32 + j*8 + tg*2;
            float b0 = bias[c], b1 = bias[c+1];
            #pragma unroll
            for (int half = 0; half < 2; half++) {
                int r = r0 + half*8;
                float v0 = acc[i][j][half*2+0] + b0;
                float v1 = acc[i][j][half*2+1] + b1;
                if (MODE == 1 || MODE == 3) {
                    if (MODE == 1) { v0 = fmaxf(v0, 0.f); v1 = fmaxf(v1, 0.f); }
                    __nv_bfloat16 h0, l0, h1, l1;
                    split_bf16(v0, h0, l0); split_bf16(v1, h1, l1);
                    __nv_bfloat162 hp; hp.x = h0; hp.y = h1;
                    __nv_bfloat162 lp; lp.x = l0; lp.y = l1;
                    *(__nv_bfloat162*)&Chi[(size_t)r * N + c] = hp;
                    *(__nv_bfloat162*)&Clo[(size_t)r * N + c] = lp;
                } else {
                    if (MODE == 2) {
                        float2 rv = *(const float2*)&res[(size_t)r * N + c];
                        v0 += rv.x; v1 += rv.y;
                    }
                    float2 o; o.x = v0; o.y = v1;
                    *(float2*)&Cf[(size_t)r * N + c] = o;
                }
            }
        }
    }
}

template<int MODE>
__global__ __launch_bounds__(256) void gemm_mma(
    const __nv_bfloat16* __restrict__ Ahi, const __nv_bfloat16* __restrict__ Alo,
    const __nv_bfloat16* __restrict__ Bhi, const __nv_bfloat16* __restrict__ Blo,
    const float* __restrict__ bias, int K, int N,
    float* __restrict__ Cf, __nv_bfloat16* __restrict__ Chi, __nv_bfloat16* __restrict__ Clo,
    const float* __restrict__ res)
{
    gemm_mma_body<MODE>(Ahi, Alo, Bhi, Blo, bias, K, N, Cf, Chi, Clo, res,
                        blockIdx.y * 128, blockIdx.x * 128);
}

__global__ __launch_bounds__(256) void gemm_mma_qkv(
    const __nv_bfloat16* __restrict__ hhi, const __nv_bfloat16* __restrict__ hlo,
    const __nv_bfloat16* __restrict__ wqh, const __nv_bfloat16* __restrict__ wql,
    const __nv_bfloat16* __restrict__ wkh, const __nv_bfloat16* __restrict__ wkl,
    const __nv_bfloat16* __restrict__ wvh, const __nv_bfloat16* __restrict__ wvl,
    const float* __restrict__ bq, const float* __restrict__ bk, const float* __restrict__ bv,
    __nv_bfloat16* qh, __nv_bfloat16* ql, __nv_bfloat16* kh, __nv_bfloat16* kl,
    __nv_bfloat16* vh, __nv_bfloat16* vl)
{
    const __nv_bfloat16 *Bh, *Bl; const float* bi; __nv_bfloat16 *Ch, *Cl;
    if (blockIdx.z == 0)      { Bh = wqh; Bl = wql; bi = bq; Ch = qh; Cl = ql; }
    else if (blockIdx.z == 1) { Bh = wkh; Bl = wkl; bi = bk; Ch = kh; Cl = kl; }
    else                      { Bh = wvh; Bl = wvl; bi = bv; Ch = vh; Cl = vl; }
    gemm_mma_body<3>(hhi, hlo, Bh, Bl, bi, EE, EE, nullptr, Ch, Cl, nullptr,
                     blockIdx.y * 128, blockIdx.x * 128);
}

// ---------------- Flash attention on mma.sync --------------------------------
// grid (SEQ/128, H, B), 256 threads = 8 warps; warp owns 16 q-rows.
// Key tiles of 32; softmax entirely in registers (intra-warp quad reductions).
__global__ __launch_bounds__(256) void flash_attn_mma(
    const __nv_bfloat16* __restrict__ qh_g, const __nv_bfloat16* __restrict__ ql_g,
    const __nv_bfloat16* __restrict__ kh_g, const __nv_bfloat16* __restrict__ kl_g,
    const __nv_bfloat16* __restrict__ vh_g, const __nv_bfloat16* __restrict__ vl_g,
    const int* __restrict__ mask, float* __restrict__ out)
{
    extern __shared__ char fsm[];
    uint32_t sQh = smem_u32(fsm);
    uint32_t sQl = sQh + FB_Q_BYTES;
    uint32_t sKV = sQl + FB_Q_BYTES;                 // 2 stages x (Kh,Kl,Vh,Vl)
    uint32_t sMk = sKV + 2*FB_STAGE;                 // 2 stages x 32 ints

    int tid = threadIdx.x, lane = tid & 31, warp = tid >> 5;
    int g = lane >> 2, tg = lane & 3;
    int q0 = blockIdx.x * 128;
    int h  = blockIdx.y;
    int b  = blockIdx.z;
    int hoff = h * DDIM;
    size_t bS = (size_t)b * SEQ;
    const int* mb = mask + bS;

    // ---- prologue: load Q (hi/lo) + KV stage 0 + mask 0 ----
    {
        int row = tid >> 3, seg = tid & 7;           // Q: 4 chunks per thread per mat
        #pragma unroll
        for (int i = 0; i < 4; i++) {
            int r = row + i * 32;
            uint32_t so = (uint32_t)r * FB_STRIDE_B + seg * 16;
            size_t ga = (bS + q0 + r) * EE + hoff + seg * 8;
            cp16(sQh + so, qh_g + ga);
            cp16(sQl + so, ql_g + ga);
        }
        // KV stage 0: mat i: 0=Kh 1=Kl 2=Vh 3=Vl; row=tid>>3, seg=tid&7
        uint32_t so = (uint32_t)(tid >> 3) * FB_STRIDE_B + seg * 16;
        size_t gk = (bS + 0 + (tid >> 3)) * EE + hoff + seg * 8;
        cp16(sKV + 0*FB_KV_MAT + so, kh_g + gk);
        cp16(sKV + 1*FB_KV_MAT + so, kl_g + gk);
        cp16(sKV + 2*FB_KV_MAT + so, vh_g + gk);
        cp16(sKV + 3*FB_KV_MAT + so, vl_g + gk);
        if (tid < 8) cp16(sMk + tid*16, mb + tid*4);
        cp_commit();
    }
    cp_wait0();
    __syncthreads();

    // ---- Q fragments to registers (resident) ----
    uint32_t qfh[4][4], qfl[4][4];
    {
        uint32_t base = (uint32_t)(warp*16 + ((lane>>3)&1)*8 + (lane&7)) * FB_STRIDE_B
                      + (lane>>4)*16;
        #pragma unroll
        for (int ks = 0; ks < 4; ks++) {
            ldmx4(qfh[ks], sQh + base + ks*32);
            ldmx4(qfl[ks], sQl + base + ks*32);
        }
    }

    float accO[8][4];
    #pragma unroll
    for (int j = 0; j < 8; j++)
        #pragma unroll
        for (int c = 0; c < 4; c++) accO[j][c] = 0.f;
    float mOld0 = -1e30f, mOld1 = -1e30f, l0 = 0.f, l1 = 0.f;

    uint32_t kAddrBase = (uint32_t)(((lane>>4)*8 + (lane&7)) * FB_STRIDE_B)
                       + ((lane>>3)&1)*16;           // + p*16 rows + ks*32 cols
    uint32_t vAddrBase = (uint32_t)((((lane>>3)&1)*8 + (lane&7)) * FB_STRIDE_B)
                       + (lane>>4)*16;               // + ks2*16 rows + ng*32 cols

    const int T = SEQ / 32;
    for (int it = 0; it < T; it++) {
        // prefetch stage it+1
        if (it + 1 < T) {
            uint32_t stg = sKV + ((it+1) & 1) * FB_STAGE;
            int seg = tid & 7;
            uint32_t so = (uint32_t)(tid >> 3) * FB_STRIDE_B + seg * 16;
            size_t gk = (bS + (it+1)*32 + (tid >> 3)) * EE + hoff + seg * 8;
            cp16(stg + 0*FB_KV_MAT + so, kh_g + gk);
            cp16(stg + 1*FB_KV_MAT + so, kl_g + gk);
            cp16(stg + 2*FB_KV_MAT + so, vh_g + gk);
            cp16(stg + 3*FB_KV_MAT + so, vl_g + gk);
            if (tid < 8) cp16(sMk + ((it+1)&1)*128 + tid*16, mb + (it+1)*32 + tid*4);
            cp_commit();
            cp_wait1();
        } else {
            cp_wait0();
        }
        __syncthreads();

        uint32_t stg = sKV + (it & 1) * FB_STAGE;
        const int* smk = (const int*)(uintptr_t)0;   // smem mask read via ptr below

        // ---- S = Q K^T : accS[4 n-tiles][4] ----
        float accS[4][4];
        #pragma unroll
        for (int j = 0; j < 4; j++)
            #pragma unroll
            for (int c = 0; c < 4; c++) accS[j][c] = 0.f;
        #pragma unroll
        for (int ks = 0; ks < 4; ks++) {
            uint32_t bh[2][4], bl[2][4];
            #pragma unroll
            for (int p = 0; p < 2; p++) {
                uint32_t ad = stg + kAddrBase + (uint32_t)p*16*FB_STRIDE_B + ks*32;
                ldmx4(bh[p], ad);
                ldmx4(bl[p], ad + FB_KV_MAT);
            }
            #pragma unroll
            for (int j = 0; j < 4; j++) {
                const uint32_t* bhp = &bh[j>>1][(j&1)*2];
                const uint32_t* blp = &bl[j>>1][(j&1)*2];
                mma_bf16(accS[j], qfh[ks], bhp);
                mma_bf16(accS[j], qfh[ks], blp);
                mma_bf16(accS[j], qfl[ks], bhp);
            }
        }

        // ---- mask + scale + online softmax (registers only) ----
        int mk0[4], mk1[4];
        {
            uint32_t mbase = sMk + (it & 1) * 128;
            #pragma unroll
            for (int j = 0; j < 4; j++) {
                int n0 = j*8 + tg*2;
                int a, bb2;
                asm volatile("ld.shared.b32 %0, [%1];" : "=r"(a)   : "r"(mbase + n0*4));
                asm volatile("ld.shared.b32 %0, [%1];" : "=r"(bb2) : "r"(mbase + n0*4 + 4));
                mk0[j] = a; mk1[j] = bb2;
            }
        }
        float mx0 = -1e30f, mx1 = -1e30f;
        #pragma unroll
        for (int j = 0; j < 4; j++) {
            accS[j][0] = mk0[j] ? -1e30f : accS[j][0] * 0.125f;
            accS[j][1] = mk1[j] ? -1e30f : accS[j][1] * 0.125f;
            accS[j][2] = mk0[j] ? -1e30f : accS[j][2] * 0.125f;
            accS[j][3] = mk1[j] ? -1e30f : accS[j][3] * 0.125f;
            mx0 = fmaxf(mx0, fmaxf(accS[j][0], accS[j][1]));
            mx1 = fmaxf(mx1, fmaxf(accS[j][2], accS[j][3]));
        }
        mx0 = fmaxf(mx0, __shfl_xor_sync(0xffffffffu, mx0, 1));
        mx0 = fmaxf(mx0, __shfl_xor_sync(0xffffffffu, mx0, 2));
        mx1 = fmaxf(mx1, __shfl_xor_sync(0xffffffffu, mx1, 1));
        mx1 = fmaxf(mx1, __shfl_xor_sync(0xffffffffu, mx1, 2));
        float mn0 = fmaxf(mOld0, mx0), mn1 = fmaxf(mOld1, mx1);
        float scl0 = __expf(mOld0 - mn0), scl1 = __expf(mOld1 - mn1);
        float p[4][4];
        float ls0 = 0.f, ls1 = 0.f;
        #pragma unroll
        for (int j = 0; j < 4; j++) {
            p[j][0] = mk0[j] ? 0.f : __expf(accS[j][0] - mn0);
            p[j][1] = mk1[j] ? 0.f : __expf(accS[j][1] - mn0);
            p[j][2] = mk0[j] ? 0.f : __expf(accS[j][2] - mn1);
            p[j][3] = mk1[j] ? 0.f : __expf(accS[j][3] - mn1);
            ls0 += p[j][0] + p[j][1];
            ls1 += p[j][2] + p[j][3];
        }
        ls0 += __shfl_xor_sync(0xffffffffu, ls0, 1);
        ls0 += __shfl_xor_sync(0xffffffffu, ls0, 2);
        ls1 += __shfl_xor_sync(0xffffffffu, ls1, 1);
        ls1 += __shfl_xor_sync(0xffffffffu, ls1, 2);
        l0 = l0 * scl0 + ls0;
        l1 = l1 * scl1 + ls1;
        mOld0 = mn0; mOld1 = mn1;
        #pragma unroll
        for (int j = 0; j < 8; j++) {
            accO[j][0] *= scl0; accO[j][1] *= scl0;
            accO[j][2] *= scl1; accO[j][3] *= scl1;
        }

        // ---- P fragments (bf16 hi/lo), direct from registers ----
        uint32_t aph[2][4], apl[2][4];
        #pragma unroll
        for (int jj = 0; jj < 2; jj++) {
            int t0 = 2*jj, t1 = 2*jj + 1;
            pack_hilo(p[t0][0], p[t0][1], aph[jj][0], apl[jj][0]);
            pack_hilo(p[t0][2], p[t0][3], aph[jj][1], apl[jj][1]);
            pack_hilo(p[t1][0], p[t1][1], aph[jj][2], apl[jj][2]);
            pack_hilo(p[t1][2], p[t1][3], aph[jj][3], apl[jj][3]);
        }

        // ---- O += P V : V b-frags via ldmatrix.trans on [k,d] ----
        #pragma unroll
        for (int ks2 = 0; ks2 < 2; ks2++) {
            uint32_t vh2[4][4], vl2[4][4];
            #pragma unroll
            for (int ng = 0; ng < 4; ng++) {
                uint32_t ad = stg + 2*FB_KV_MAT + vAddrBase
                            + (uint32_t)ks2*16*FB_STRIDE_B + ng*32;
                ldmx4t(vh2[ng], ad);
                ldmx4t(vl2[ng], ad + FB_KV_MAT);
            }
            #pragma unroll
            for (int jd = 0; jd < 8; jd++) {
                const uint32_t* bvh = &vh2[jd>>1][(jd&1)*2];
                const uint32_t* bvl = &vl2[jd>>1][(jd&1)*2];
                mma_bf16(accO[jd], aph[ks2], bvh);
                mma_bf16(accO[jd], aph[ks2], bvl);
                mma_bf16(accO[jd], apl[ks2], bvh);
            }
        }
        __syncthreads();
    }

    // ---- epilogue ----
    float inv0 = 1.f / l0, inv1 = 1.f / l1;
    size_t row0 = bS + q0 + warp*16 + g;
    #pragma unroll
    for (int jd = 0; jd < 8; jd++) {
        int c = hoff + jd*8 + tg*2;
        float2 o0; o0.x = accO[jd][0] * inv0; o0.y = accO[jd][1] * inv0;
        float2 o1; o1.x = accO[jd][2] * inv1; o1.y = accO[jd][3] * inv1;
        *(float2*)&out[row0 * EE + c]       = o0;
        *(float2*)&out[(row0 + 8) * EE + c] = o1;
    }
}

// ---------------- misc ------------------------------------------------------
__global__ void copy_f4(const float4* __restrict__ in, float4* __restrict__ out, int n4) {
    int i = blockIdx.x * blockDim.x + threadIdx.x;
    if (i < n4) out[i] = in[i];
}

// ---------------- launch ----------------------------------------------------
extern "C" void kernel_launch(void* const* d_in, const int* in_sizes, int n_in,
                              void* d_out, int out_size) {
    const float* x_in = (const float*)d_in[0];
    const int* mask = (const int*)d_in[1];
    const float* wq = (const float*)d_in[2];
    const float* bq = (const float*)d_in[3];
    const float* wk = (const float*)d_in[4];
    const float* bk = (const float*)d_in[5];
    const float* wv = (const float*)d_in[6];
    const float* bv = (const float*)d_in[7];
    const float* g1 = (const float*)d_in[8];
    const float* b1 = (const float*)d_in[9];
    const float* g2 = (const float*)d_in[10];
    const float* b2 = (const float*)d_in[11];
    const float* gf = (const float*)d_in[12];
    const float* bf = (const float*)d_in[13];
    const float* W1 = (const float*)d_in[14];
    const float* B1 = (const float*)d_in[15];
    const float* W2 = (const float*)d_in[16];
    const float* B2 = (const float*)d_in[17];
    float* outp = (float*)d_out;

    float *px, *pattn;
    __nv_bfloat16 *pqh, *pql, *pkh, *pkl, *pvh, *pvl;
    __nv_bfloat16 *phhi, *phlo, *pfhi, *pflo;
    __nv_bfloat16 *pwqh, *pwql, *pwkh, *pwkl, *pwvh, *pwvl, *pW1h, *pW1l, *pW2h, *pW2l;
    cudaGetSymbolAddress((void**)&px,    g_x);
    cudaGetSymbolAddress((void**)&pattn, g_attn);
    cudaGetSymbolAddress((void**)&pqh,   g_qhi);
    cudaGetSymbolAddress((void**)&pql,   g_qlo);
    cudaGetSymbolAddress((void**)&pkh,   g_khi);
    cudaGetSymbolAddress((void**)&pkl,   g_klo);
    cudaGetSymbolAddress((void**)&pvh,   g_vhi);
    cudaGetSymbolAddress((void**)&pvl,   g_vlo);
    cudaGetSymbolAddress((void**)&phhi,  g_hhi);
    cudaGetSymbolAddress((void**)&phlo,  g_hlo);
    cudaGetSymbolAddress((void**)&pfhi,  g_fhi);
    cudaGetSymbolAddress((void**)&pflo,  g_flo);
    cudaGetSymbolAddress((void**)&pwqh,  g_wqhi);
    cudaGetSymbolAddress((void**)&pwql,  g_wqlo);
    cudaGetSymbolAddress((void**)&pwkh,  g_wkhi);
    cudaGetSymbolAddress((void**)&pwkl,  g_wklo);
    cudaGetSymbolAddress((void**)&pwvh,  g_wvhi);
    cudaGetSymbolAddress((void**)&pwvl,  g_wvlo);
    cudaGetSymbolAddress((void**)&pW1h,  g_W1hi);
    cudaGetSymbolAddress((void**)&pW1l,  g_W1lo);
    cudaGetSymbolAddress((void**)&pW2h,  g_W2hi);
    cudaGetSymbolAddress((void**)&pW2l,  g_W2lo);

    cudaFuncSetAttribute(flash_attn_mma,
                         cudaFuncAttributeMaxDynamicSharedMemorySize, FB_SMEM);
    cudaFuncSetAttribute(gemm_mma_qkv,
                         cudaFuncAttributeMaxDynamicSharedMemorySize, GM_SMEM);
    cudaFuncSetAttribute(gemm_mma<1>,
                         cudaFuncAttributeMaxDynamicSharedMemorySize, GM_SMEM);
    cudaFuncSetAttribute(gemm_mma<2>,
                         cudaFuncAttributeMaxDynamicSharedMemorySize, GM_SMEM);

    {
        int n4 = NROWS * EE / 4;
        copy_f4<<<(n4 + 255) / 256, 256>>>((const float4*)x_in, (float4*)px, n4);
    }
    {
        int nq = NLAYERS * EE * EE;
        cvt_kernel<<<(nq + 255) / 256, 256>>>(wq, pwqh, pwql, nq);
        cvt_kernel<<<(nq + 255) / 256, 256>>>(wk, pwkh, pwkl, nq);
        cvt_kernel<<<(nq + 255) / 256, 256>>>(wv, pwvh, pwvl, nq);
        int n1 = DFFN * EE;
        cvt_kernel<<<(n1 + 255) / 256, 256>>>(W1, pW1h, pW1l, n1);
        int n2 = EE * DFFN;
        cvt_kernel<<<(n2 + 255) / 256, 256>>>(W2, pW2h, pW2l, n2);
    }

    dim3 gQKV(EE / 128, NROWS / 128, 3);   // (4, 32, 3)
    dim3 gFF1(DFFN / 128, NROWS / 128);    // (16, 32)
    dim3 gFF2(EE / 128, NROWS / 128);      // (4, 32)
    dim3 gAtt(SEQ / 128, HH, BB);          // (16, 8, 2)

    for (int l = 0; l < NLAYERS; l++) {
        const __nv_bfloat16* wqh = pwqh + (size_t)l * EE * EE;
        const __nv_bfloat16* wql = pwql + (size_t)l * EE * EE;
        const __nv_bfloat16* wkh = pwkh + (size_t)l * EE * EE;
        const __nv_bfloat16* wkl = pwkl + (size_t)l * EE * EE;
        const __nv_bfloat16* wvh = pwvh + (size_t)l * EE * EE;
        const __nv_bfloat16* wvl = pwvl + (size_t)l * EE * EE;
        const float* bql = bq + (size_t)l * EE;
        const float* bkl = bk + (size_t)l * EE;
        const float* bvl = bv + (size_t)l * EE;

        ln_bf16<<<NROWS, 128>>>(px, phhi, phlo, g1, b1);
        gemm_mma_qkv<<<gQKV, 256, GM_SMEM>>>(phhi, phlo,
            wqh, wql, wkh, wkl, wvh, wvl, bql, bkl, bvl,
            pqh, pql, pkh, pkl, pvh, pvl);
        flash_attn_mma<<<gAtt, 256, FB_SMEM>>>(pqh, pql, pkh, pkl, pvh, pvl,
                                               mask, pattn);
        fuse_attn_res_ln<<<NROWS, 128>>>(pattn, px, phhi, phlo, g2, b2);
        gemm_mma<1><<<gFF1, 256, GM_SMEM>>>(phhi, phlo, pW1h, pW1l,
            B1, EE, DFFN, nullptr, pfhi, pflo, nullptr);
        gemm_mma<2><<<gFF2, 256, GM_SMEM>>>(pfhi, pflo, pW2h, pW2l,
            B2, DFFN, EE, px, nullptr, nullptr, px);
    }
    ln_f32<<<NROWS, 128>>>(px, outp, gf, bf);
}

// round 10
// speedup vs baseline: 5.0104x; 1.2773x over previous
#include <cuda_runtime.h>
#include <cuda_bf16.h>
#include <stdint.h>

#define BB      2
#define SEQ     2048
#define EE      512
#define HH      8
#define DDIM    64
#define NLAYERS 2
#define DFFN    2048
#define NROWS   4096   // BB*SEQ

// mma.sync GEMM config: 128x128 tile, K-chunk 32 (bf16), hi/lo x3 passes
#define GM_CHUNK     32
#define GM_STRIDE    80
#define GM_MAT_BYTES (128 * GM_STRIDE)
#define GM_BUF_BYTES (4 * GM_MAT_BYTES)
#define GM_SMEM      (2 * GM_BUF_BYTES)

// flash mma config: BQ=128, BK=32, 8 warps (16 q-rows each)
#define FB_STRIDE_B  144                   // 64 bf16 = 128B + 16B pad
#define FB_Q_BYTES   (128 * FB_STRIDE_B)   // 18432 per matrix (hi or lo)
#define FB_KV_MAT    (32 * FB_STRIDE_B)    // 4608
#define FB_STAGE     (4 * FB_KV_MAT)       // Kh,Kl,Vh,Vl = 18432
#define FB_SMEM      (2*FB_Q_BYTES + 2*FB_STAGE + 256)

// ---------------- scratch (device globals) ----------------------------------
__device__ float g_x[NROWS * EE];
__device__ float g_attn[NROWS * EE];
__device__ __nv_bfloat16 g_qhi[NROWS*EE], g_qlo[NROWS*EE];
__device__ __nv_bfloat16 g_khi[NROWS*EE], g_klo[NROWS*EE];
__device__ __nv_bfloat16 g_vhi[NROWS*EE], g_vlo[NROWS*EE];
__device__ __nv_bfloat16 g_ckh[NROWS*EE], g_ckl[NROWS*EE];   // compacted K hi/lo
__device__ __nv_bfloat16 g_cvh[NROWS*EE], g_cvl[NROWS*EE];   // compacted V hi/lo
__device__ int g_cnt[BB];
__device__ int g_cidx[BB*SEQ];
__device__ __nv_bfloat16 g_hhi[NROWS * EE];
__device__ __nv_bfloat16 g_hlo[NROWS * EE];
__device__ __nv_bfloat16 g_fhi[NROWS * DFFN];
__device__ __nv_bfloat16 g_flo[NROWS * DFFN];
__device__ __nv_bfloat16 g_wqhi[NLAYERS*EE*EE], g_wqlo[NLAYERS*EE*EE];
__device__ __nv_bfloat16 g_wkhi[NLAYERS*EE*EE], g_wklo[NLAYERS*EE*EE];
__device__ __nv_bfloat16 g_wvhi[NLAYERS*EE*EE], g_wvlo[NLAYERS*EE*EE];
__device__ __nv_bfloat16 g_W1hi[DFFN*EE], g_W1lo[DFFN*EE];
__device__ __nv_bfloat16 g_W2hi[EE*DFFN], g_W2lo[EE*DFFN];

// ---------------- PTX helpers ------------------------------------------------
__device__ __forceinline__ uint32_t smem_u32(const void* p) {
    uint32_t a;
    asm("{ .reg .u64 t; cvta.to.shared.u64 t, %1; cvt.u32.u64 %0, t; }" : "=r"(a) : "l"(p));
    return a;
}
__device__ __forceinline__ void cp16(uint32_t saddr, const void* g) {
    asm volatile("cp.async.cg.shared.global [%0], [%1], 16;" :: "r"(saddr), "l"(g));
}
__device__ __forceinline__ void cp_commit() {
    asm volatile("cp.async.commit_group;" ::: "memory");
}
__device__ __forceinline__ void cp_wait0() {
    asm volatile("cp.async.wait_group 0;" ::: "memory");
}
__device__ __forceinline__ void cp_wait1() {
    asm volatile("cp.async.wait_group 1;" ::: "memory");
}
__device__ __forceinline__ void ldmx4(uint32_t* r, uint32_t addr) {
    asm volatile("ldmatrix.sync.aligned.m8n8.x4.shared.b16 {%0,%1,%2,%3}, [%4];"
        : "=r"(r[0]), "=r"(r[1]), "=r"(r[2]), "=r"(r[3]) : "r"(addr));
}
__device__ __forceinline__ void ldmx4t(uint32_t* r, uint32_t addr) {
    asm volatile("ldmatrix.sync.aligned.m8n8.x4.trans.shared.b16 {%0,%1,%2,%3}, [%4];"
        : "=r"(r[0]), "=r"(r[1]), "=r"(r[2]), "=r"(r[3]) : "r"(addr));
}
__device__ __forceinline__ void mma_bf16(float* d, const uint32_t* a, const uint32_t* b) {
    asm volatile(
        "mma.sync.aligned.m16n8k16.row.col.f32.bf16.bf16.f32 "
        "{%0,%1,%2,%3}, {%4,%5,%6,%7}, {%8,%9}, {%0,%1,%2,%3};"
        : "+f"(d[0]), "+f"(d[1]), "+f"(d[2]), "+f"(d[3])
        : "r"(a[0]), "r"(a[1]), "r"(a[2]), "r"(a[3]), "r"(b[0]), "r"(b[1]));
}

// ---------------- hi/lo split ------------------------------------------------
__device__ __forceinline__ void split_bf16(float v, __nv_bfloat16& h, __nv_bfloat16& l) {
    h = __float2bfloat16(v);
    l = __float2bfloat16(v - __bfloat162float(h));
}
__device__ __forceinline__ void pack_hilo(float a, float b, uint32_t& h, uint32_t& l) {
    __nv_bfloat162 hp, lp;
    hp.x = __float2bfloat16(a);
    hp.y = __float2bfloat16(b);
    lp.x = __float2bfloat16(a - __bfloat162float(hp.x));
    lp.y = __float2bfloat16(b - __bfloat162float(hp.y));
    h = *reinterpret_cast<uint32_t*>(&hp);
    l = *reinterpret_cast<uint32_t*>(&lp);
}

// ---------------- reductions -------------------------------------------------
__device__ __forceinline__ void block_reduce2(float& s, float& s2) {
    __shared__ float shm[8];
    #pragma unroll
    for (int o = 16; o > 0; o >>= 1) {
        s  += __shfl_down_sync(0xffffffffu, s,  o);
        s2 += __shfl_down_sync(0xffffffffu, s2, o);
    }
    int w = threadIdx.x >> 5;
    __syncthreads();
    if ((threadIdx.x & 31) == 0) { shm[w] = s; shm[4 + w] = s2; }
    __syncthreads();
    s  = shm[0] + shm[1] + shm[2] + shm[3];
    s2 = shm[4] + shm[5] + shm[6] + shm[7];
}

// ---------------- LayerNorm variants ----------------------------------------
__global__ void ln_f32(const float* __restrict__ in, float* __restrict__ outp,
                       const float* __restrict__ g, const float* __restrict__ b) {
    int row = blockIdx.x, t = threadIdx.x;
    const float* xr = in + (size_t)row * EE;
    float v[4], s = 0.f, s2 = 0.f;
    #pragma unroll
    for (int i = 0; i < 4; i++) { v[i] = xr[t + i*128]; s += v[i]; s2 += v[i]*v[i]; }
    block_reduce2(s, s2);
    float mu = s * (1.f/EE), var = s2 * (1.f/EE) - mu*mu, r = rsqrtf(var + 1e-5f);
    #pragma unroll
    for (int i = 0; i < 4; i++) {
        int idx = t + i*128;
        outp[(size_t)row*EE + idx] = (v[i]-mu)*r*g[idx] + b[idx];
    }
}
__global__ void ln_bf16(const float* __restrict__ in,
                        __nv_bfloat16* __restrict__ hi, __nv_bfloat16* __restrict__ lo,
                        const float* __restrict__ g, const float* __restrict__ b) {
    int row = blockIdx.x, t = threadIdx.x;
    const float* xr = in + (size_t)row * EE;
    float v[4], s = 0.f, s2 = 0.f;
    #pragma unroll
    for (int i = 0; i < 4; i++) { v[i] = xr[t + i*128]; s += v[i]; s2 += v[i]*v[i]; }
    block_reduce2(s, s2);
    float mu = s * (1.f/EE), var = s2 * (1.f/EE) - mu*mu, r = rsqrtf(var + 1e-5f);
    #pragma unroll
    for (int i = 0; i < 4; i++) {
        int idx = t + i*128;
        float y = (v[i]-mu)*r*g[idx] + b[idx];
        __nv_bfloat16 h, l; split_bf16(y, h, l);
        hi[(size_t)row*EE + idx] = h;
        lo[(size_t)row*EE + idx] = l;
    }
}
__global__ void fuse_attn_res_ln(const float* __restrict__ attn, float* x,
                                 __nv_bfloat16* __restrict__ hhi, __nv_bfloat16* __restrict__ hlo,
                                 const float* __restrict__ g2, const float* __restrict__ b2) {
    int row = blockIdx.x, t = threadIdx.x;
    const float* ar = attn + (size_t)row * EE;
    float a[4], s = 0.f, s2 = 0.f;
    #pragma unroll
    for (int i = 0; i < 4; i++) { a[i] = ar[t + i*128]; s += a[i]; s2 += a[i]*a[i]; }
    block_reduce2(s, s2);
    float mu = s * (1.f/EE), var = s2 * (1.f/EE) - mu*mu, r = rsqrtf(var + 1e-5f);
    float xv[4];
    s = 0.f; s2 = 0.f;
    #pragma unroll
    for (int i = 0; i < 4; i++) {
        int idx = t + i*128;
        float y = (a[i]-mu)*r*g2[idx] + b2[idx];
        float xn = x[(size_t)row*EE + idx] + y;
        x[(size_t)row*EE + idx] = xn;
        xv[i] = xn; s += xn; s2 += xn*xn;
    }
    block_reduce2(s, s2);
    float mu2 = s * (1.f/EE), var2 = s2 * (1.f/EE) - mu2*mu2, r2 = rsqrtf(var2 + 1e-5f);
    #pragma unroll
    for (int i = 0; i < 4; i++) {
        int idx = t + i*128;
        float y = (xv[i]-mu2)*r2;
        __nv_bfloat16 h, l; split_bf16(y, h, l);
        hhi[(size_t)row*EE + idx] = h;
        hlo[(size_t)row*EE + idx] = l;
    }
}

// ---------------- weight fp32 -> bf16 hi/lo ---------------------------------
__global__ void cvt_kernel(const float* __restrict__ in,
                           __nv_bfloat16* __restrict__ hi, __nv_bfloat16* __restrict__ lo, int n) {
    int i = blockIdx.x * blockDim.x + threadIdx.x;
    if (i < n) {
        __nv_bfloat16 h, l; split_bf16(in[i], h, l);
        hi[i] = h; lo[i] = l;
    }
}

// ---------------- mask compaction --------------------------------------------
// one block per batch, 1024 threads, 2 key positions each; Hillis-Steele scan
__global__ __launch_bounds__(1024) void compact_idx(const int* __restrict__ mask) {
    __shared__ int part[1024];
    int b = blockIdx.x, t = threadIdx.x;
    const int* mb = mask + (size_t)b * SEQ;
    int v0 = (mb[2*t]   == 0);
    int v1 = (mb[2*t+1] == 0);
    part[t] = v0 + v1;
    __syncthreads();
    for (int o = 1; o < 1024; o <<= 1) {
        int x = part[t];
        int y = (t >= o) ? part[t-o] : 0;
        __syncthreads();
        part[t] = x + y;
        __syncthreads();
    }
    int incl = part[t];
    int excl = incl - (v0 + v1);
    if (v0) g_cidx[b*SEQ + excl]      = 2*t;
    if (v1) g_cidx[b*SEQ + excl + v0] = 2*t+1;
    if (t == 1023) g_cnt[b] = incl;
}

// gather unmasked K/V rows into dense buffers; zero-pad to 32-row multiple.
// grid (SEQ, BB), 256 threads: m = t>>6 selects matrix, c = t&63 selects uint4.
__global__ __launch_bounds__(256) void compact_copy(
    const __nv_bfloat16* __restrict__ kh, const __nv_bfloat16* __restrict__ kl,
    const __nv_bfloat16* __restrict__ vh, const __nv_bfloat16* __restrict__ vl) {
    int b = blockIdx.y, j = blockIdx.x, t = threadIdx.x;
    int cnt = g_cnt[b];
    int lim = (cnt + 31) & ~31;
    if (j >= lim) return;
    int m = t >> 6, c = t & 63;
    size_t dst = ((size_t)b * SEQ + j) * EE + c * 8;
    const __nv_bfloat16* sp;
    __nv_bfloat16* dp;
    if      (m == 0) dp = g_ckh;
    else if (m == 1) dp = g_ckl;
    else if (m == 2) dp = g_cvh;
    else             dp = g_cvl;
    if (j < cnt) {
        int src = g_cidx[b*SEQ + j];
        size_t sof = ((size_t)b * SEQ + src) * EE + c * 8;
        if      (m == 0) sp = kh;
        else if (m == 1) sp = kl;
        else if (m == 2) sp = vh;
        else             sp = vl;
        *(uint4*)(dp + dst) = *(const uint4*)(sp + sof);
    } else {
        uint4 z; z.x = 0; z.y = 0; z.z = 0; z.w = 0;
        *(uint4*)(dp + dst) = z;
    }
}

// ---------------- mma.sync GEMM ----------------------------------------------
// MODE 1: bias+relu -> bf16 hi/lo. MODE 2: fp32+bias+residual. MODE 3: bias -> bf16 hi/lo.
template<int MODE>
__device__ __forceinline__ void gemm_mma_body(
    const __nv_bfloat16* __restrict__ Ahi, const __nv_bfloat16* __restrict__ Alo,
    const __nv_bfloat16* __restrict__ Bhi, const __nv_bfloat16* __restrict__ Blo,
    const float* __restrict__ bias, int K, int N,
    float* __restrict__ Cf, __nv_bfloat16* __restrict__ Chi, __nv_bfloat16* __restrict__ Clo,
    const float* __restrict__ res, int rowBase, int colBase)
{
    extern __shared__ char sm8[];
    uint32_t sbase = smem_u32(sm8);
    int tid = threadIdx.x, lane = tid & 31, warp = tid >> 5;
    int wm = warp >> 2, wn = warp & 3;

    float acc[4][4][4];
    #pragma unroll
    for (int i = 0; i < 4; i++)
        #pragma unroll
        for (int j = 0; j < 4; j++)
            #pragma unroll
            for (int c = 0; c < 4; c++) acc[i][j][c] = 0.f;

    uint32_t aAddr = (uint32_t)((wm*64 + ((lane>>3)&1)*8 + (lane&7)) * GM_STRIDE
                                + (lane>>4)*16);
    uint32_t bAddr = (uint32_t)((wn*32 + (lane>>4)*8 + (lane&7)) * GM_STRIDE
                                + ((lane>>3)&1)*16);

    const int T = K / GM_CHUNK;
    int lrow0 = tid >> 2, lseg = tid & 3;

    {
        uint32_t sb = sbase;
        #pragma unroll
        for (int j = 0; j < 2; j++) {
            int row = lrow0 + j*64;
            uint32_t so = row*GM_STRIDE + lseg*16;
            size_t ga = (size_t)(rowBase+row)*K + lseg*8;
            size_t gb = (size_t)(colBase+row)*K + lseg*8;
            cp16(sb + 0*GM_MAT_BYTES + so, Ahi + ga);
            cp16(sb + 1*GM_MAT_BYTES + so, Alo + ga);
            cp16(sb + 2*GM_MAT_BYTES + so, Bhi + gb);
            cp16(sb + 3*GM_MAT_BYTES + so, Blo + gb);
        }
        cp_commit();
    }

    for (int t = 0; t < T; t++) {
        cp_wait0();
        __syncthreads();
        if (t + 1 < T) {
            uint32_t sb = sbase + ((t+1) & 1) * GM_BUF_BYTES;
            int koff = (t+1) * GM_CHUNK;
            #pragma unroll
            for (int j = 0; j < 2; j++) {
                int row = lrow0 + j*64;
                uint32_t so = row*GM_STRIDE + lseg*16;
                size_t ga = (size_t)(rowBase+row)*K + koff + lseg*8;
                size_t gb = (size_t)(colBase+row)*K + koff + lseg*8;
                cp16(sb + 0*GM_MAT_BYTES + so, Ahi + ga);
                cp16(sb + 1*GM_MAT_BYTES + so, Alo + ga);
                cp16(sb + 2*GM_MAT_BYTES + so, Bhi + gb);
                cp16(sb + 3*GM_MAT_BYTES + so, Blo + gb);
            }
            cp_commit();
        }
        uint32_t buf = sbase + (t & 1) * GM_BUF_BYTES;
        #pragma unroll
        for (int ks = 0; ks < 2; ks++) {
            uint32_t ah[4][4], al[4][4], bh[2][4], bl[2][4];
            #pragma unroll
            for (int i = 0; i < 4; i++) {
                uint32_t ad = buf + aAddr + i*16*GM_STRIDE + ks*32;
                ldmx4(ah[i], ad);
                ldmx4(al[i], ad + GM_MAT_BYTES);
            }
            #pragma unroll
            for (int p = 0; p < 2; p++) {
                uint32_t bd = buf + 2*GM_MAT_BYTES + bAddr + p*16*GM_STRIDE + ks*32;
                ldmx4(bh[p], bd);
                ldmx4(bl[p], bd + GM_MAT_BYTES);
            }
            #pragma unroll
            for (int i = 0; i < 4; i++)
                #pragma unroll
                for (int j = 0; j < 4; j++) {
                    const uint32_t* bhp = &bh[j>>1][(j&1)*2];
                    const uint32_t* blp = &bl[j>>1][(j&1)*2];
                    mma_bf16(acc[i][j], ah[i], bhp);
                    mma_bf16(acc[i][j], ah[i], blp);
                    mma_bf16(acc[i][j], al[i], bhp);
                }
        }
    }

    int g = lane >> 2, tg = lane & 3;
    #pragma unroll
    for (int i = 0; i < 4; i++) {
        int r0 = rowBase + wm*64 + i*16 + g;
        #pragma unroll
        for (int j = 0; j < 4; j++) {
            int c = colBase + wn*32 + j*8 + tg*2;
            float b0 = bias[c], b1 = bias[c+1];
            #pragma unroll
            for (int half = 0; half < 2; half++) {
                int r = r0 + half*8;
                float v0 = acc[i][j][half*2+0] + b0;
                float v1 = acc[i][j][half*2+1] + b1;
                if (MODE == 1 || MODE == 3) {
                    if (MODE == 1) { v0 = fmaxf(v0, 0.f); v1 = fmaxf(v1, 0.f); }
                    __nv_bfloat16 h0, l0, h1, l1;
                    split_bf16(v0, h0, l0); split_bf16(v1, h1, l1);
                    __nv_bfloat162 hp; hp.x = h0; hp.y = h1;
                    __nv_bfloat162 lp; lp.x = l0; lp.y = l1;
                    *(__nv_bfloat162*)&Chi[(size_t)r * N + c] = hp;
                    *(__nv_bfloat162*)&Clo[(size_t)r * N + c] = lp;
                } else {
                    if (MODE == 2) {
                        float2 rv = *(const float2*)&res[(size_t)r * N + c];
                        v0 += rv.x; v1 += rv.y;
                    }
                    float2 o; o.x = v0; o.y = v1;
                    *(float2*)&Cf[(size_t)r * N + c] = o;
                }
            }
        }
    }
}

template<int MODE>
__global__ __launch_bounds__(256) void gemm_mma(
    const __nv_bfloat16* __restrict__ Ahi, const __nv_bfloat16* __restrict__ Alo,
    const __nv_bfloat16* __restrict__ Bhi, const __nv_bfloat16* __restrict__ Blo,
    const float* __restrict__ bias, int K, int N,
    float* __restrict__ Cf, __nv_bfloat16* __restrict__ Chi, __nv_bfloat16* __restrict__ Clo,
    const float* __restrict__ res)
{
    gemm_mma_body<MODE>(Ahi, Alo, Bhi, Blo, bias, K, N, Cf, Chi, Clo, res,
                        blockIdx.y * 128, blockIdx.x * 128);
}

__global__ __launch_bounds__(256) void gemm_mma_qkv(
    const __nv_bfloat16* __restrict__ hhi, const __nv_bfloat16* __restrict__ hlo,
    const __nv_bfloat16* __restrict__ wqh, const __nv_bfloat16* __restrict__ wql,
    const __nv_bfloat16* __restrict__ wkh, const __nv_bfloat16* __restrict__ wkl,
    const __nv_bfloat16* __restrict__ wvh, const __nv_bfloat16* __restrict__ wvl,
    const float* __restrict__ bq, const float* __restrict__ bk, const float* __restrict__ bv,
    __nv_bfloat16* qh, __nv_bfloat16* ql, __nv_bfloat16* kh, __nv_bfloat16* kl,
    __nv_bfloat16* vh, __nv_bfloat16* vl)
{
    const __nv_bfloat16 *Bh, *Bl; const float* bi; __nv_bfloat16 *Ch, *Cl;
    if (blockIdx.z == 0)      { Bh = wqh; Bl = wql; bi = bq; Ch = qh; Cl = ql; }
    else if (blockIdx.z == 1) { Bh = wkh; Bl = wkl; bi = bk; Ch = kh; Cl = kl; }
    else                      { Bh = wvh; Bl = wvl; bi = bv; Ch = vh; Cl = vl; }
    gemm_mma_body<3>(hhi, hlo, Bh, Bl, bi, EE, EE, nullptr, Ch, Cl, nullptr,
                     blockIdx.y * 128, blockIdx.x * 128);
}

// ---------------- Flash attention on mma.sync + compacted keys ---------------
// grid (SEQ/128, H, B), 256 threads = 8 warps; warp owns 16 q-rows.
// Key tiles of 32 over the compacted (unmasked) keys; dynamic trip count.
__global__ __launch_bounds__(256) void flash_attn_mma(
    const __nv_bfloat16* __restrict__ qh_g, const __nv_bfloat16* __restrict__ ql_g,
    float* __restrict__ out)
{
    extern __shared__ char fsm[];
    uint32_t sQh = smem_u32(fsm);
    uint32_t sQl = sQh + FB_Q_BYTES;
    uint32_t sKV = sQl + FB_Q_BYTES;                 // 2 stages x (Kh,Kl,Vh,Vl)

    int tid = threadIdx.x, lane = tid & 31, warp = tid >> 5;
    int g = lane >> 2, tg = lane & 3;
    int q0 = blockIdx.x * 128;
    int h  = blockIdx.y;
    int b  = blockIdx.z;
    int hoff = h * DDIM;
    size_t bS = (size_t)b * SEQ;

    int cnt = g_cnt[b];
    const int T = (cnt + 31) >> 5;

    // ---- prologue: load Q (hi/lo) + KV stage 0 ----
    {
        int row = tid >> 3, seg = tid & 7;
        #pragma unroll
        for (int i = 0; i < 4; i++) {
            int r = row + i * 32;
            uint32_t so = (uint32_t)r * FB_STRIDE_B + seg * 16;
            size_t ga = (bS + q0 + r) * EE + hoff + seg * 8;
            cp16(sQh + so, qh_g + ga);
            cp16(sQl + so, ql_g + ga);
        }
        uint32_t so = (uint32_t)(tid >> 3) * FB_STRIDE_B + seg * 16;
        size_t gk = (bS + (tid >> 3)) * EE + hoff + seg * 8;
        cp16(sKV + 0*FB_KV_MAT + so, g_ckh + gk);
        cp16(sKV + 1*FB_KV_MAT + so, g_ckl + gk);
        cp16(sKV + 2*FB_KV_MAT + so, g_cvh + gk);
        cp16(sKV + 3*FB_KV_MAT + so, g_cvl + gk);
        cp_commit();
    }
    cp_wait0();
    __syncthreads();

    // ---- Q fragments to registers (resident) ----
    uint32_t qfh[4][4], qfl[4][4];
    {
        uint32_t base = (uint32_t)(warp*16 + ((lane>>3)&1)*8 + (lane&7)) * FB_STRIDE_B
                      + (lane>>4)*16;
        #pragma unroll
        for (int ks = 0; ks < 4; ks++) {
            ldmx4(qfh[ks], sQh + base + ks*32);
            ldmx4(qfl[ks], sQl + base + ks*32);
        }
    }

    float accO[8][4];
    #pragma unroll
    for (int j = 0; j < 8; j++)
        #pragma unroll
        for (int c = 0; c < 4; c++) accO[j][c] = 0.f;
    float mOld0 = -1e30f, mOld1 = -1e30f, l0 = 0.f, l1 = 0.f;

    uint32_t kAddrBase = (uint32_t)(((lane>>4)*8 + (lane&7)) * FB_STRIDE_B)
                       + ((lane>>3)&1)*16;
    uint32_t vAddrBase = (uint32_t)((((lane>>3)&1)*8 + (lane&7)) * FB_STRIDE_B)
                       + (lane>>4)*16;

    for (int it = 0; it < T; it++) {
        if (it + 1 < T) {
            uint32_t stg2 = sKV + ((it+1) & 1) * FB_STAGE;
            int seg = tid & 7;
            uint32_t so = (uint32_t)(tid >> 3) * FB_STRIDE_B + seg * 16;
            size_t gk = (bS + (it+1)*32 + (tid >> 3)) * EE + hoff + seg * 8;
            cp16(stg2 + 0*FB_KV_MAT + so, g_ckh + gk);
            cp16(stg2 + 1*FB_KV_MAT + so, g_ckl + gk);
            cp16(stg2 + 2*FB_KV_MAT + so, g_cvh + gk);
            cp16(stg2 + 3*FB_KV_MAT + so, g_cvl + gk);
            cp_commit();
            cp_wait1();
        } else {
            cp_wait0();
        }
        __syncthreads();

        uint32_t stg = sKV + (it & 1) * FB_STAGE;

        // ---- S = Q K^T ----
        float accS[4][4];
        #pragma unroll
        for (int j = 0; j < 4; j++)
            #pragma unroll
            for (int c = 0; c < 4; c++) accS[j][c] = 0.f;
        #pragma unroll
        for (int ks = 0; ks < 4; ks++) {
            uint32_t bh[2][4], bl[2][4];
            #pragma unroll
            for (int p = 0; p < 2; p++) {
                uint32_t ad = stg + kAddrBase + (uint32_t)p*16*FB_STRIDE_B + ks*32;
                ldmx4(bh[p], ad);
                ldmx4(bl[p], ad + FB_KV_MAT);
            }
            #pragma unroll
            for (int j = 0; j < 4; j++) {
                const uint32_t* bhp = &bh[j>>1][(j&1)*2];
                const uint32_t* blp = &bl[j>>1][(j&1)*2];
                mma_bf16(accS[j], qfh[ks], bhp);
                mma_bf16(accS[j], qfh[ks], blp);
                mma_bf16(accS[j], qfl[ks], bhp);
            }
        }

        // ---- scale (+ tail clamp) + online softmax in registers ----
        int lim = cnt - it*32;
        if (lim >= 32) {
            #pragma unroll
            for (int j = 0; j < 4; j++) {
                accS[j][0] *= 0.125f; accS[j][1] *= 0.125f;
                accS[j][2] *= 0.125f; accS[j][3] *= 0.125f;
            }
        } else {
            #pragma unroll
            for (int j = 0; j < 4; j++) {
                int n0 = j*8 + tg*2;
                bool k0 = n0 < lim, k1 = (n0 + 1) < lim;
                accS[j][0] = k0 ? accS[j][0]*0.125f : -1e30f;
                accS[j][1] = k1 ? accS[j][1]*0.125f : -1e30f;
                accS[j][2] = k0 ? accS[j][2]*0.125f : -1e30f;
                accS[j][3] = k1 ? accS[j][3]*0.125f : -1e30f;
            }
        }
        float mx0 = -1e30f, mx1 = -1e30f;
        #pragma unroll
        for (int j = 0; j < 4; j++) {
            mx0 = fmaxf(mx0, fmaxf(accS[j][0], accS[j][1]));
            mx1 = fmaxf(mx1, fmaxf(accS[j][2], accS[j][3]));
        }
        mx0 = fmaxf(mx0, __shfl_xor_sync(0xffffffffu, mx0, 1));
        mx0 = fmaxf(mx0, __shfl_xor_sync(0xffffffffu, mx0, 2));
        mx1 = fmaxf(mx1, __shfl_xor_sync(0xffffffffu, mx1, 1));
        mx1 = fmaxf(mx1, __shfl_xor_sync(0xffffffffu, mx1, 2));
        float mn0 = fmaxf(mOld0, mx0), mn1 = fmaxf(mOld1, mx1);
        float scl0 = __expf(mOld0 - mn0), scl1 = __expf(mOld1 - mn1);
        float p[4][4];
        float ls0 = 0.f, ls1 = 0.f;
        #pragma unroll
        for (int j = 0; j < 4; j++) {
            p[j][0] = __expf(accS[j][0] - mn0);
            p[j][1] = __expf(accS[j][1] - mn0);
            p[j][2] = __expf(accS[j][2] - mn1);
            p[j][3] = __expf(accS[j][3] - mn1);
            ls0 += p[j][0] + p[j][1];
            ls1 += p[j][2] + p[j][3];
        }
        ls0 += __shfl_xor_sync(0xffffffffu, ls0, 1);
        ls0 += __shfl_xor_sync(0xffffffffu, ls0, 2);
        ls1 += __shfl_xor_sync(0xffffffffu, ls1, 1);
        ls1 += __shfl_xor_sync(0xffffffffu, ls1, 2);
        l0 = l0 * scl0 + ls0;
        l1 = l1 * scl1 + ls1;
        mOld0 = mn0; mOld1 = mn1;
        #pragma unroll
        for (int j = 0; j < 8; j++) {
            accO[j][0] *= scl0; accO[j][1] *= scl0;
            accO[j][2] *= scl1; accO[j][3] *= scl1;
        }

        // ---- P fragments (bf16 hi/lo) ----
        uint32_t aph[2][4], apl[2][4];
        #pragma unroll
        for (int jj = 0; jj < 2; jj++) {
            int t0 = 2*jj, t1 = 2*jj + 1;
            pack_hilo(p[t0][0], p[t0][1], aph[jj][0], apl[jj][0]);
            pack_hilo(p[t0][2], p[t0][3], aph[jj][1], apl[jj][1]);
            pack_hilo(p[t1][0], p[t1][1], aph[jj][2], apl[jj][2]);
            pack_hilo(p[t1][2], p[t1][3], aph[jj][3], apl[jj][3]);
        }

        // ---- O += P V ----
        #pragma unroll
        for (int ks2 = 0; ks2 < 2; ks2++) {
            uint32_t vh2[4][4], vl2[4][4];
            #pragma unroll
            for (int ng = 0; ng < 4; ng++) {
                uint32_t ad = stg + 2*FB_KV_MAT + vAddrBase
                            + (uint32_t)ks2*16*FB_STRIDE_B + ng*32;
                ldmx4t(vh2[ng], ad);
                ldmx4t(vl2[ng], ad + FB_KV_MAT);
            }
            #pragma unroll
            for (int jd = 0; jd < 8; jd++) {
                const uint32_t* bvh = &vh2[jd>>1][(jd&1)*2];
                const uint32_t* bvl = &vl2[jd>>1][(jd&1)*2];
                mma_bf16(accO[jd], aph[ks2], bvh);
                mma_bf16(accO[jd], aph[ks2], bvl);
                mma_bf16(accO[jd], apl[ks2], bvh);
            }
        }
        __syncthreads();
    }

    // ---- epilogue ----
    float inv0 = 1.f / l0, inv1 = 1.f / l1;
    size_t row0 = bS + q0 + warp*16 + g;
    #pragma unroll
    for (int jd = 0; jd < 8; jd++) {
        int c = hoff + jd*8 + tg*2;
        float2 o0; o0.x = accO[jd][0] * inv0; o0.y = accO[jd][1] * inv0;
        float2 o1; o1.x = accO[jd][2] * inv1; o1.y = accO[jd][3] * inv1;
        *(float2*)&out[row0 * EE + c]       = o0;
        *(float2*)&out[(row0 + 8) * EE + c] = o1;
    }
}

// ---------------- misc ------------------------------------------------------
__global__ void copy_f4(const float4* __restrict__ in, float4* __restrict__ out, int n4) {
    int i = blockIdx.x * blockDim.x + threadIdx.x;
    if (i < n4) out[i] = in[i];
}

// ---------------- launch ----------------------------------------------------
extern "C" void kernel_launch(void* const* d_in, const int* in_sizes, int n_in,
                              void* d_out, int out_size) {
    const float* x_in = (const float*)d_in[0];
    const int* mask = (const int*)d_in[1];
    const float* wq = (const float*)d_in[2];
    const float* bq = (const float*)d_in[3];
    const float* wk = (const float*)d_in[4];
    const float* bk = (const float*)d_in[5];
    const float* wv = (const float*)d_in[6];
    const float* bv = (const float*)d_in[7];
    const float* g1 = (const float*)d_in[8];
    const float* b1 = (const float*)d_in[9];
    const float* g2 = (const float*)d_in[10];
    const float* b2 = (const float*)d_in[11];
    const float* gf = (const float*)d_in[12];
    const float* bf = (const float*)d_in[13];
    const float* W1 = (const float*)d_in[14];
    const float* B1 = (const float*)d_in[15];
    const float* W2 = (const float*)d_in[16];
    const float* B2 = (const float*)d_in[17];
    float* outp = (float*)d_out;

    float *px, *pattn;
    __nv_bfloat16 *pqh, *pql, *pkh, *pkl, *pvh, *pvl;
    __nv_bfloat16 *phhi, *phlo, *pfhi, *pflo;
    __nv_bfloat16 *pwqh, *pwql, *pwkh, *pwkl, *pwvh, *pwvl, *pW1h, *pW1l, *pW2h, *pW2l;
    cudaGetSymbolAddress((void**)&px,    g_x);
    cudaGetSymbolAddress((void**)&pattn, g_attn);
    cudaGetSymbolAddress((void**)&pqh,   g_qhi);
    cudaGetSymbolAddress((void**)&pql,   g_qlo);
    cudaGetSymbolAddress((void**)&pkh,   g_khi);
    cudaGetSymbolAddress((void**)&pkl,   g_klo);
    cudaGetSymbolAddress((void**)&pvh,   g_vhi);
    cudaGetSymbolAddress((void**)&pvl,   g_vlo);
    cudaGetSymbolAddress((void**)&phhi,  g_hhi);
    cudaGetSymbolAddress((void**)&phlo,  g_hlo);
    cudaGetSymbolAddress((void**)&pfhi,  g_fhi);
    cudaGetSymbolAddress((void**)&pflo,  g_flo);
    cudaGetSymbolAddress((void**)&pwqh,  g_wqhi);
    cudaGetSymbolAddress((void**)&pwql,  g_wqlo);
    cudaGetSymbolAddress((void**)&pwkh,  g_wkhi);
    cudaGetSymbolAddress((void**)&pwkl,  g_wklo);
    cudaGetSymbolAddress((void**)&pwvh,  g_wvhi);
    cudaGetSymbolAddress((void**)&pwvl,  g_wvlo);
    cudaGetSymbolAddress((void**)&pW1h,  g_W1hi);
    cudaGetSymbolAddress((void**)&pW1l,  g_W1lo);
    cudaGetSymbolAddress((void**)&pW2h,  g_W2hi);
    cudaGetSymbolAddress((void**)&pW2l,  g_W2lo);

    cudaFuncSetAttribute(flash_attn_mma,
                         cudaFuncAttributeMaxDynamicSharedMemorySize, FB_SMEM);
    cudaFuncSetAttribute(gemm_mma_qkv,
                         cudaFuncAttributeMaxDynamicSharedMemorySize, GM_SMEM);
    cudaFuncSetAttribute(gemm_mma<1>,
                         cudaFuncAttributeMaxDynamicSharedMemorySize, GM_SMEM);
    cudaFuncSetAttribute(gemm_mma<2>,
                         cudaFuncAttributeMaxDynamicSharedMemorySize, GM_SMEM);

    {
        int n4 = NROWS * EE / 4;
        copy_f4<<<(n4 + 255) / 256, 256>>>((const float4*)x_in, (float4*)px, n4);
    }
    {
        int nq = NLAYERS * EE * EE;
        cvt_kernel<<<(nq + 255) / 256, 256>>>(wq, pwqh, pwql, nq);
        cvt_kernel<<<(nq + 255) / 256, 256>>>(wk, pwkh, pwkl, nq);
        cvt_kernel<<<(nq + 255) / 256, 256>>>(wv, pwvh, pwvl, nq);
        int n1 = DFFN * EE;
        cvt_kernel<<<(n1 + 255) / 256, 256>>>(W1, pW1h, pW1l, n1);
        int n2 = EE * DFFN;
        cvt_kernel<<<(n2 + 255) / 256, 256>>>(W2, pW2h, pW2l, n2);
    }
    compact_idx<<<BB, 1024>>>(mask);       // mask is layer-invariant

    dim3 gQKV(EE / 128, NROWS / 128, 3);   // (4, 32, 3)
    dim3 gFF1(DFFN / 128, NROWS / 128);    // (16, 32)
    dim3 gFF2(EE / 128, NROWS / 128);      // (4, 32)
    dim3 gAtt(SEQ / 128, HH, BB);          // (16, 8, 2)
    dim3 gCpy(SEQ, BB);

    for (int l = 0; l < NLAYERS; l++) {
        const __nv_bfloat16* wqh = pwqh + (size_t)l * EE * EE;
        const __nv_bfloat16* wql = pwql + (size_t)l * EE * EE;
        const __nv_bfloat16* wkh = pwkh + (size_t)l * EE * EE;
        const __nv_bfloat16* wkl = pwkl + (size_t)l * EE * EE;
        const __nv_bfloat16* wvh = pwvh + (size_t)l * EE * EE;
        const __nv_bfloat16* wvl = pwvl + (size_t)l * EE * EE;
        const float* bql = bq + (size_t)l * EE;
        const float* bkl = bk + (size_t)l * EE;
        const float* bvl = bv + (size_t)l * EE;

        ln_bf16<<<NROWS, 128>>>(px, phhi, phlo, g1, b1);
        gemm_mma_qkv<<<gQKV, 256, GM_SMEM>>>(phhi, phlo,
            wqh, wql, wkh, wkl, wvh, wvl, bql, bkl, bvl,
            pqh, pql, pkh, pkl, pvh, pvl);
        compact_copy<<<gCpy, 256>>>(pkh, pkl, pvh, pvl);
        flash_attn_mma<<<gAtt, 256, FB_SMEM>>>(pqh, pql, pattn);
        fuse_attn_res_ln<<<NROWS, 128>>>(pattn, px, phhi, phlo, g2, b2);
        gemm_mma<1><<<gFF1, 256, GM_SMEM>>>(phhi, phlo, pW1h, pW1l,
            B1, EE, DFFN, nullptr, pfhi, pflo, nullptr);
        gemm_mma<2><<<gFF2, 256, GM_SMEM>>>(pfhi, pflo, pW2h, pW2l,
            B2, DFFN, EE, px, nullptr, nullptr, px);
    }
    ln_f32<<<NROWS, 128>>>(px, outp, gf, bf);
}